// round 7
// baseline (speedup 1.0000x reference)
#include <cuda_runtime.h>
#include <cuda_bf16.h>
#include <math.h>
#include <stdint.h>

#define N_NODES 50000
#define N_EDGES 800000
#define DIM 128

typedef unsigned long long ull;
typedef unsigned short u16;

// ---------------- scratch ----------------
__device__ float g_h[(size_t)N_NODES * DIM];         // aggr + x  (gemm1 input)
__device__ float g_h1[(size_t)N_NODES * 256];        // h @ W1.T
__device__ float g_PQ[(size_t)N_NODES * 256];        // [P | Q] per node
__device__ float2 g_edge[(size_t)N_EDGES];           // sorted (src_as_float, ea)
__device__ int2 g_eid2[(size_t)N_EDGES];             // sorted (orig_eid, dst)
__device__ int g_cnt[N_NODES];
__device__ int g_off[N_NODES];
__device__ int g_cur[N_NODES];
__device__ float g_bnsum[512];
__device__ float g_bnstat[512];
// pre-split bf16 weights, [k][n] layout, padded rows
__device__ __align__(16) u16 g_B1h[128 * 264], g_B1l[128 * 264];   // W1:  k<128, n<256, stride 264
__device__ __align__(16) u16 g_B3h[128 * 264], g_B3l[128 * 264];   // We-remap: k<128, n<256
__device__ __align__(16) u16 g_B2h[256 * 136], g_B2l[256 * 136];   // W2:  k<256, n<128, stride 136

// ---------------- mma helpers ----------------
__device__ __forceinline__ uint32_t smem_u32(const void* p) {
    uint32_t a;
    asm("{ .reg .u64 t; cvta.to.shared.u64 t, %1; cvt.u32.u64 %0, t; }" : "=r"(a) : "l"(p));
    return a;
}
__device__ __forceinline__ void ldmx4(uint32_t* r, uint32_t addr) {
    asm volatile("ldmatrix.sync.aligned.m8n8.x4.shared.b16 {%0,%1,%2,%3}, [%4];"
        : "=r"(r[0]), "=r"(r[1]), "=r"(r[2]), "=r"(r[3]) : "r"(addr));
}
__device__ __forceinline__ void ldmx4t(uint32_t* r, uint32_t addr) {
    asm volatile("ldmatrix.sync.aligned.m8n8.x4.trans.shared.b16 {%0,%1,%2,%3}, [%4];"
        : "=r"(r[0]), "=r"(r[1]), "=r"(r[2]), "=r"(r[3]) : "r"(addr));
}
__device__ __forceinline__ void mma16816(float* c, const uint32_t* a, uint32_t b0, uint32_t b1) {
    asm volatile("mma.sync.aligned.m16n8k16.row.col.f32.bf16.bf16.f32 "
        "{%0,%1,%2,%3}, {%4,%5,%6,%7}, {%8,%9}, {%0,%1,%2,%3};"
        : "+f"(c[0]), "+f"(c[1]), "+f"(c[2]), "+f"(c[3])
        : "r"(a[0]), "r"(a[1]), "r"(a[2]), "r"(a[3]), "r"(b0), "r"(b1));
}
__device__ __forceinline__ void split2(float a, float b, uint32_t& uh, uint32_t& ul) {
    __nv_bfloat16 h0 = __float2bfloat16_rn(a), h1 = __float2bfloat16_rn(b);
    float r0 = a - __bfloat162float(h0), r1 = b - __bfloat162float(h1);
    __nv_bfloat16 l0 = __float2bfloat16_rn(r0), l1 = __float2bfloat16_rn(r1);
    uh = (uint32_t)(*(u16*)&h0) | ((uint32_t)(*(u16*)&h1) << 16);
    ul = (uint32_t)(*(u16*)&l0) | ((uint32_t)(*(u16*)&l1) << 16);
}
__device__ __forceinline__ void redg(float* p, float v) {
    asm volatile("red.global.add.f32 [%0], %1;" :: "l"(p), "f"(v) : "memory");
}

// SMEM layout (bytes)
#define CTRL 4096
#define ASTR 272                       // A row stride: 128 bf16 + 8 pad
#define OFF_AH CTRL
#define OFF_AL (OFF_AH + 128 * ASTR)
#define OFF_BH (OFF_AL + 128 * ASTR)
#define SM_TC256 (OFF_BH + 2 * 67584)
#define SM_MLP2  (OFF_BH + 2 * 69632)

// ---------------- weight prep ----------------
__global__ void __launch_bounds__(256) prep_w256(
    const float* __restrict__ W, u16* __restrict__ Bh, u16* __restrict__ Bl, int mode)
{
    int i = blockIdx.x * 256 + threadIdx.x;
    if (i >= 256 * 128) return;
    int j = i >> 7, k = i & 127;
    float v = (mode == 0) ? W[j * 128 + k]
            : ((j < 128) ? W[j * 256 + k] : W[(j - 128) * 256 + 128 + k]);
    __nv_bfloat16 hb = __float2bfloat16_rn(v);
    float rr = v - __bfloat162float(hb);
    __nv_bfloat16 lb = __float2bfloat16_rn(rr);
    Bh[k * 264 + j] = *(u16*)&hb;
    Bl[k * 264 + j] = *(u16*)&lb;
}
__global__ void __launch_bounds__(256) prep_w2(const float* __restrict__ W)
{
    int i = blockIdx.x * 256 + threadIdx.x;
    if (i >= 128 * 256) return;
    int j = i >> 8, k = i & 255;
    float v = W[i];
    __nv_bfloat16 hb = __float2bfloat16_rn(v);
    float rr = v - __bfloat162float(hb);
    __nv_bfloat16 lb = __float2bfloat16_rn(rr);
    g_B2h[k * 136 + j] = *(u16*)&hb;
    g_B2l[k * 136 + j] = *(u16*)&lb;
}

// ---------------- edge sort: hist / scan / scatter ----------------
__global__ void __launch_bounds__(256) hist(const int* __restrict__ dst)
{
    int e = blockIdx.x * 256 + threadIdx.x;
    if (e < N_EDGES) atomicAdd(&g_cnt[dst[e]], 1);
}

__global__ void __launch_bounds__(1024) scan50k()
{
    __shared__ int wsum[32];
    __shared__ int sh_carry;
    int tid = threadIdx.x, lane = tid & 31, w = tid >> 5;
    if (tid == 0) sh_carry = 0;
    __syncthreads();
    for (int base = 0; base < N_NODES; base += 1024) {
        int i = base + tid;
        int v = (i < N_NODES) ? g_cnt[i] : 0;
        int x = v;
#pragma unroll
        for (int o = 1; o < 32; o <<= 1) { int y = __shfl_up_sync(~0u, x, o); if (lane >= o) x += y; }
        if (lane == 31) wsum[w] = x;
        __syncthreads();
        if (w == 0) {
            int s = wsum[lane];
#pragma unroll
            for (int o = 1; o < 32; o <<= 1) { int y = __shfl_up_sync(~0u, s, o); if (lane >= o) s += y; }
            wsum[lane] = s;
        }
        __syncthreads();
        int warp_excl = (w == 0) ? 0 : wsum[w - 1];
        int carry = sh_carry;
        int excl = carry + warp_excl + x - v;
        if (i < N_NODES) { g_off[i] = excl; g_cur[i] = excl; }
        __syncthreads();
        if (tid == 1023) sh_carry = carry + wsum[31];
        __syncthreads();
    }
}

__global__ void __launch_bounds__(256) scatter(
    const int* __restrict__ src, const int* __restrict__ dst, const float* __restrict__ ea)
{
    int e = blockIdx.x * 256 + threadIdx.x;
    if (e >= N_EDGES) return;
    int d = dst[e];
    int pos = atomicAdd(&g_cur[d], 1);
    g_edge[pos] = make_float2(__int_as_float(src[e]), ea[e]);
    g_eid2[pos] = make_int2(e, d);
}

// ---------------- aggregate: warp per node -> g_h = softmax-aggr + x ----------------
__global__ void __launch_bounds__(256) aggregate(
    const float* __restrict__ x, const float* __restrict__ W_edge, const float* __restrict__ tptr)
{
    int gw = (blockIdx.x * 256 + threadIdx.x) >> 5;
    int lane = threadIdx.x & 31;
    if (gw >= N_NODES) return;
    const float t = tptr[0];
    float4 w4 = *(const float4*)&W_edge[lane * 4];

    int beg = g_off[gw];
    int end = (gw == N_NODES - 1) ? N_EDGES : g_off[gw + 1];

    float4 aE = make_float4(0.f, 0.f, 0.f, 0.f);
    float4 aM = make_float4(0.f, 0.f, 0.f, 0.f);

    for (int b = beg; b < end; b += 32) {
        int j = b + lane;
        float2 ed = (j < end) ? g_edge[j] : make_float2(0.f, 0.f);
        int cnt = min(32, end - b);
        for (int q = 0; q < cnt; q++) {
            int s   = __shfl_sync(0xffffffffu, __float_as_int(ed.x), q);
            float a = __shfl_sync(0xffffffffu, ed.y, q);
            float4 xv = *(const float4*)&x[(size_t)s * DIM + lane * 4];
            float m0 = fmaxf(fmaf(a, w4.x, xv.x), 0.f) + 1e-7f;
            float m1 = fmaxf(fmaf(a, w4.y, xv.y), 0.f) + 1e-7f;
            float m2 = fmaxf(fmaf(a, w4.z, xv.z), 0.f) + 1e-7f;
            float m3 = fmaxf(fmaf(a, w4.w, xv.w), 0.f) + 1e-7f;
            float e0 = __expf(m0 * t), e1 = __expf(m1 * t);
            float e2 = __expf(m2 * t), e3 = __expf(m3 * t);
            aE.x += e0; aE.y += e1; aE.z += e2; aE.w += e3;
            aM.x = fmaf(m0, e0, aM.x); aM.y = fmaf(m1, e1, aM.y);
            aM.z = fmaf(m2, e2, aM.z); aM.w = fmaf(m3, e3, aM.w);
        }
    }
    float4 xn = *(const float4*)&x[(size_t)gw * DIM + lane * 4];
    float4 h;
    h.x = aM.x / (aE.x + 1e-16f) + xn.x;
    h.y = aM.y / (aE.y + 1e-16f) + xn.y;
    h.z = aM.z / (aE.z + 1e-16f) + xn.z;
    h.w = aM.w / (aE.w + 1e-16f) + xn.w;
    *(float4*)&g_h[(size_t)gw * DIM + lane * 4] = h;
}

// ============================================================================
// tc256: out[rows x 256] = in[rows x 128] @ B[256 x 128]^T via mma.sync bf16 split
// 512 threads, tile 128 rows. Optional BN column-stat accumulation (do_bn).
// ============================================================================
__global__ void __launch_bounds__(512, 1) tc256(
    const float* __restrict__ in, const u16* __restrict__ Bh, const u16* __restrict__ Bl,
    float* __restrict__ out, int do_bn)
{
    extern __shared__ __align__(16) char sm[];
    uint32_t sb = smem_u32(sm);
    int tid = threadIdx.x, wid = tid >> 5, lane = tid & 31;
    int row0 = blockIdx.x * 128;

    {
        const float4* bh = (const float4*)Bh;
        const float4* bl = (const float4*)Bl;
        float4* sh = (float4*)(sm + OFF_BH);
        float4* sl = (float4*)(sm + OFF_BH + 67584);
        for (int i = tid; i < 4224; i += 512) { sh[i] = bh[i]; sl[i] = bl[i]; }
    }
    for (int i = tid; i < 128 * 64; i += 512) {
        int r = i >> 6, k2 = (i & 63) << 1;
        int row = row0 + r;
        float2 hv = make_float2(0.f, 0.f);
        if (row < N_NODES) hv = *(const float2*)&in[(size_t)row * 128 + k2];
        uint32_t uh, ul;
        split2(hv.x, hv.y, uh, ul);
        *(uint32_t*)(sm + OFF_AH + r * ASTR + k2 * 2) = uh;
        *(uint32_t*)(sm + OFF_AL + r * ASTR + k2 * 2) = ul;
    }
    __syncthreads();

    int mrow0 = (wid & 7) * 16, nh = wid >> 3;
    uint32_t aRow = mrow0 + (lane & 7) + ((lane >> 3) & 1) * 8;
    uint32_t aAddrH = sb + OFF_AH + aRow * ASTR + (lane >> 4) * 16;
    uint32_t aAddrL = aAddrH + (OFF_AL - OFF_AH);
    uint32_t bLaneRow = (lane & 7) + ((lane >> 3) & 1) * 8;
    uint32_t bLaneN = ((lane >> 4) & 1) * 16 + nh * 256;

    float c[16][4];
#pragma unroll
    for (int t = 0; t < 16; t++)
#pragma unroll
        for (int q = 0; q < 4; q++) c[t][q] = 0.f;

#pragma unroll
    for (int kst = 0; kst < 8; kst++) {
        uint32_t ah[4], al[4];
        ldmx4(ah, aAddrH + kst * 32);
        ldmx4(al, aAddrL + kst * 32);
        uint32_t bAddr = sb + OFF_BH + (kst * 16 + bLaneRow) * 528 + bLaneN;
#pragma unroll
        for (int tp = 0; tp < 8; tp++) {
            uint32_t bh[4], bl[4];
            ldmx4t(bh, bAddr + tp * 32);
            ldmx4t(bl, bAddr + tp * 32 + 67584);
            mma16816(c[2 * tp],     ah, bh[0], bh[1]);
            mma16816(c[2 * tp],     al, bh[0], bh[1]);
            mma16816(c[2 * tp],     ah, bl[0], bl[1]);
            mma16816(c[2 * tp + 1], ah, bh[2], bh[3]);
            mma16816(c[2 * tp + 1], al, bh[2], bh[3]);
            mma16816(c[2 * tp + 1], ah, bl[2], bl[3]);
        }
    }

    int rbase = row0 + mrow0 + (lane >> 2);
    int cbase = nh * 128 + (lane & 3) * 2;
#pragma unroll
    for (int t = 0; t < 16; t++) {
        int n0 = cbase + t * 8;
        if (rbase < N_NODES)     *(float2*)&out[(size_t)rbase * 256 + n0]       = make_float2(c[t][0], c[t][1]);
        if (rbase + 8 < N_NODES) *(float2*)&out[(size_t)(rbase + 8) * 256 + n0] = make_float2(c[t][2], c[t][3]);
    }

    // BN column stats fold (OOB rows already produce exact zeros -> harmless)
    if (do_bn) {
        float s0[16], q0[16], s1[16], q1[16];
#pragma unroll
        for (int t = 0; t < 16; t++) {
            s0[t] = c[t][0] + c[t][2];
            q0[t] = c[t][0] * c[t][0] + c[t][2] * c[t][2];
            s1[t] = c[t][1] + c[t][3];
            q1[t] = c[t][1] * c[t][1] + c[t][3] * c[t][3];
        }
#pragma unroll
        for (int o = 4; o < 32; o <<= 1) {
#pragma unroll
            for (int t = 0; t < 16; t++) {
                s0[t] += __shfl_xor_sync(~0u, s0[t], o);
                q0[t] += __shfl_xor_sync(~0u, q0[t], o);
                s1[t] += __shfl_xor_sync(~0u, s1[t], o);
                q1[t] += __shfl_xor_sync(~0u, q1[t], o);
            }
        }
        if ((lane >> 2) == 0) {
#pragma unroll
            for (int t = 0; t < 16; t++) {
                int n0 = cbase + t * 8;
                redg(&g_bnsum[n0], s0[t]);
                redg(&g_bnsum[256 + n0], q0[t]);
                redg(&g_bnsum[n0 + 1], s1[t]);
                redg(&g_bnsum[256 + n0 + 1], q1[t]);
            }
        }
    }
}

__global__ void bn_stat(const float* __restrict__ bng, const float* __restrict__ bnb)
{
    int j = threadIdx.x;
    float s = g_bnsum[j], s2 = g_bnsum[256 + j];
    float mu = s * (1.0f / N_NODES);
    float var = s2 * (1.0f / N_NODES) - mu * mu;
    float rstd = rsqrtf(var + 1e-5f);
    float sc = rstd * bng[j];
    g_bnstat[j] = sc;
    g_bnstat[256 + j] = bnb[j] - mu * sc;
}

__device__ __forceinline__ float elu1(float v) { return v > 0.f ? v : expm1f(v); }

// ============================================================================
// tc_mlp2: out_x = ELU(LN(relu(bn(g_h1)) @ W2.T))
// ============================================================================
__global__ void __launch_bounds__(512, 1) tc_mlp2(
    const float* __restrict__ lng, const float* __restrict__ lnb, float* __restrict__ out_x)
{
    extern __shared__ __align__(16) char sm[];
    uint32_t sb = smem_u32(sm);
    int tid = threadIdx.x, wid = tid >> 5, lane = tid & 31;
    int row0 = blockIdx.x * 128;

    float* red  = (float*)sm;            // [128][4]
    float* lngs = (float*)(sm + 2048);
    float* lnbs = (float*)(sm + 2560);
    if (tid < 128) { lngs[tid] = lng[tid]; lnbs[tid] = lnb[tid]; }

    {
        const float4* bh = (const float4*)g_B2h;
        const float4* bl = (const float4*)g_B2l;
        float4* sh = (float4*)(sm + OFF_BH);
        float4* sl = (float4*)(sm + OFF_BH + 69632);
        for (int i = tid; i < 4352; i += 512) { sh[i] = bh[i]; sl[i] = bl[i]; }
    }

    int mrow0 = (wid & 7) * 16, nh = wid >> 3;
    uint32_t aRow = mrow0 + (lane & 7) + ((lane >> 3) & 1) * 8;
    uint32_t aAddrH = sb + OFF_AH + aRow * ASTR + (lane >> 4) * 16;
    uint32_t aAddrL = aAddrH + (OFF_AL - OFF_AH);
    uint32_t bLaneRow = (lane & 7) + ((lane >> 3) & 1) * 8;
    uint32_t bLaneN = ((lane >> 4) & 1) * 16 + nh * 128;

    float c[8][4];
#pragma unroll
    for (int t = 0; t < 8; t++)
#pragma unroll
        for (int q = 0; q < 4; q++) c[t][q] = 0.f;

#pragma unroll
    for (int s = 0; s < 2; s++) {
        __syncthreads();
        for (int i = tid; i < 128 * 64; i += 512) {
            int r = i >> 6, k2 = (i & 63) << 1;
            int row = row0 + r;
            float v0 = 0.f, v1 = 0.f;
            if (row < N_NODES) {
                int kc = s * 128 + k2;
                float2 hv = *(const float2*)&g_h1[(size_t)row * 256 + kc];
                v0 = fmaxf(fmaf(hv.x, g_bnstat[kc],     g_bnstat[256 + kc]),     0.f);
                v1 = fmaxf(fmaf(hv.y, g_bnstat[kc + 1], g_bnstat[256 + kc + 1]), 0.f);
            }
            uint32_t uh, ul;
            split2(v0, v1, uh, ul);
            *(uint32_t*)(sm + OFF_AH + r * ASTR + k2 * 2) = uh;
            *(uint32_t*)(sm + OFF_AL + r * ASTR + k2 * 2) = ul;
        }
        __syncthreads();

#pragma unroll
        for (int kst = 0; kst < 8; kst++) {
            uint32_t ah[4], al[4];
            ldmx4(ah, aAddrH + kst * 32);
            ldmx4(al, aAddrL + kst * 32);
            uint32_t bAddr = sb + OFF_BH + (s * 128 + kst * 16 + bLaneRow) * 272 + bLaneN;
#pragma unroll
            for (int tp = 0; tp < 4; tp++) {
                uint32_t bh[4], bl[4];
                ldmx4t(bh, bAddr + tp * 32);
                ldmx4t(bl, bAddr + tp * 32 + 69632);
                mma16816(c[2 * tp],     ah, bh[0], bh[1]);
                mma16816(c[2 * tp],     al, bh[0], bh[1]);
                mma16816(c[2 * tp],     ah, bl[0], bl[1]);
                mma16816(c[2 * tp + 1], ah, bh[2], bh[3]);
                mma16816(c[2 * tp + 1], al, bh[2], bh[3]);
                mma16816(c[2 * tp + 1], ah, bl[2], bl[3]);
            }
        }
    }

    float s1a = 0.f, s2a = 0.f, s1b = 0.f, s2b = 0.f;
#pragma unroll
    for (int t = 0; t < 8; t++) {
        s1a += c[t][0] + c[t][1];
        s2a += c[t][0] * c[t][0] + c[t][1] * c[t][1];
        s1b += c[t][2] + c[t][3];
        s2b += c[t][2] * c[t][2] + c[t][3] * c[t][3];
    }
#pragma unroll
    for (int o = 1; o < 4; o <<= 1) {
        s1a += __shfl_xor_sync(~0u, s1a, o);
        s2a += __shfl_xor_sync(~0u, s2a, o);
        s1b += __shfl_xor_sync(~0u, s1b, o);
        s2b += __shfl_xor_sync(~0u, s2b, o);
    }
    __syncthreads();
    if ((lane & 3) == 0) {
        int r = mrow0 + (lane >> 2);
        red[r * 4 + nh * 2]           = s1a;
        red[r * 4 + nh * 2 + 1]       = s2a;
        red[(r + 8) * 4 + nh * 2]     = s1b;
        red[(r + 8) * 4 + nh * 2 + 1] = s2b;
    }
    __syncthreads();
    {
        int ra = mrow0 + (lane >> 2), rb = ra + 8;
        float mua = (red[ra * 4] + red[ra * 4 + 2]) * (1.f / 128.f);
        float vara = (red[ra * 4 + 1] + red[ra * 4 + 3]) * (1.f / 128.f) - mua * mua;
        float rsa = rsqrtf(vara + 1e-5f);
        float mub = (red[rb * 4] + red[rb * 4 + 2]) * (1.f / 128.f);
        float varb = (red[rb * 4 + 1] + red[rb * 4 + 3]) * (1.f / 128.f) - mub * mub;
        float rsb = rsqrtf(varb + 1e-5f);
        int rowa = row0 + ra, rowb = row0 + rb;
#pragma unroll
        for (int t = 0; t < 8; t++) {
            int col = nh * 64 + t * 8 + (lane & 3) * 2;
            if (rowa < N_NODES) {
                float2 o;
                o.x = elu1((c[t][0] - mua) * rsa * lngs[col]     + lnbs[col]);
                o.y = elu1((c[t][1] - mua) * rsa * lngs[col + 1] + lnbs[col + 1]);
                *(float2*)&out_x[(size_t)rowa * DIM + col] = o;
            }
            if (rowb < N_NODES) {
                float2 o;
                o.x = elu1((c[t][2] - mub) * rsb * lngs[col]     + lnbs[col]);
                o.y = elu1((c[t][3] - mub) * rsb * lngs[col + 1] + lnbs[col + 1]);
                *(float2*)&out_x[(size_t)rowb * DIM + col] = o;
            }
        }
    }
}

// ---------------- edge_out (dst-sorted order; Q row hot in L1) ----------------
__global__ void __launch_bounds__(256) edge_out(
    const float* __restrict__ be, const float* __restrict__ lng, const float* __restrict__ lnb,
    float* __restrict__ out_e)
{
    int tid = threadIdx.x;
    int lane = tid & 31;
    int j0 = lane * 4;
    float4 bev = *(const float4*)(be + j0);
    float4 gv  = *(const float4*)(lng + j0);
    float4 bv  = *(const float4*)(lnb + j0);

    int i = blockIdx.x * 8 + (tid >> 5);
    if (i >= N_EDGES) return;
    float2 ed = g_edge[i];
    int2 info = g_eid2[i];
    int s = __float_as_int(ed.x);
    int eid = info.x, d = info.y;

    float4 p = *(const float4*)(g_PQ + (size_t)s * 256 + j0);
    float4 q = *(const float4*)(g_PQ + (size_t)d * 256 + 128 + j0);
    float g0, g1, g2, g3;
    {
        float v0 = p.x + q.x + bev.x;
        float v1 = p.y + q.y + bev.y;
        float v2 = p.z + q.z + bev.z;
        float v3 = p.w + q.w + bev.w;
        g0 = 0.5f * v0 * (1.f + erff(v0 * 0.70710678118654752f));
        g1 = 0.5f * v1 * (1.f + erff(v1 * 0.70710678118654752f));
        g2 = 0.5f * v2 * (1.f + erff(v2 * 0.70710678118654752f));
        g3 = 0.5f * v3 * (1.f + erff(v3 * 0.70710678118654752f));
    }
    float s1 = g0 + g1 + g2 + g3;
    float s2 = g0 * g0 + g1 * g1 + g2 * g2 + g3 * g3;
#pragma unroll
    for (int o = 16; o > 0; o >>= 1) {
        s1 += __shfl_xor_sync(0xffffffffu, s1, o);
        s2 += __shfl_xor_sync(0xffffffffu, s2, o);
    }
    float mu = s1 * (1.f / 128.f);
    float var = s2 * (1.f / 128.f) - mu * mu;
    float rstd = rsqrtf(var + 1e-5f);
    float4 o;
    o.x = (g0 - mu) * rstd * gv.x + bv.x;
    o.y = (g1 - mu) * rstd * gv.y + bv.y;
    o.z = (g2 - mu) * rstd * gv.z + bv.z;
    o.w = (g3 - mu) * rstd * gv.w + bv.w;
    *(float4*)(out_e + (size_t)eid * DIM + j0) = o;
}

// ---------------- launch ----------------
extern "C" void kernel_launch(void* const* d_in, const int* in_sizes, int n_in,
                              void* d_out, int out_size)
{
    const float* x      = (const float*)d_in[0];
    const int*   ei     = (const int*)  d_in[1];
    const float* ea     = (const float*)d_in[2];
    const float* W_edge = (const float*)d_in[3];
    const float* tptr   = (const float*)d_in[4];
    const float* W1     = (const float*)d_in[5];
    const float* bng    = (const float*)d_in[6];
    const float* bnb    = (const float*)d_in[7];
    const float* W2     = (const float*)d_in[8];
    const float* lng    = (const float*)d_in[9];
    const float* lnb    = (const float*)d_in[10];
    const float* We     = (const float*)d_in[11];
    const float* be     = (const float*)d_in[12];
    const float* lneg   = (const float*)d_in[13];
    const float* lneb   = (const float*)d_in[14];

    const int* src = ei;
    const int* dst = ei + N_EDGES;

    float* out_x = (float*)d_out;
    float* out_e = out_x + (size_t)N_NODES * DIM;

    void *cntp, *bnp, *b1h, *b1l, *b3h, *b3l, *ghp, *h1p, *pqp;
    cudaGetSymbolAddress(&cntp, g_cnt);
    cudaGetSymbolAddress(&bnp, g_bnsum);
    cudaGetSymbolAddress(&b1h, g_B1h); cudaGetSymbolAddress(&b1l, g_B1l);
    cudaGetSymbolAddress(&b3h, g_B3h); cudaGetSymbolAddress(&b3l, g_B3l);
    cudaGetSymbolAddress(&ghp, g_h);
    cudaGetSymbolAddress(&h1p, g_h1);
    cudaGetSymbolAddress(&pqp, g_PQ);
    cudaMemsetAsync(cntp, 0, sizeof(int) * N_NODES, 0);
    cudaMemsetAsync(bnp, 0, sizeof(float) * 512, 0);

    cudaFuncSetAttribute(tc256, cudaFuncAttributeMaxDynamicSharedMemorySize, SM_TC256);
    cudaFuncSetAttribute(tc_mlp2, cudaFuncAttributeMaxDynamicSharedMemorySize, SM_MLP2);

    int eblocks256 = (N_EDGES + 255) / 256;
    int eblocks = (N_EDGES + 7) / 8;
    int ablocks = (N_NODES * 32 + 255) / 256;
    int tblocks = (N_NODES + 127) / 128;

    prep_w256<<<128, 256>>>(W1, (u16*)b1h, (u16*)b1l, 0);
    prep_w256<<<128, 256>>>(We, (u16*)b3h, (u16*)b3l, 1);
    prep_w2<<<128, 256>>>(W2);

    hist<<<eblocks256, 256>>>(dst);
    scan50k<<<1, 1024>>>();
    scatter<<<eblocks256, 256>>>(src, dst, ea);
    aggregate<<<ablocks, 256>>>(x, W_edge, tptr);

    tc256<<<tblocks, 512, SM_TC256>>>((const float*)ghp, (const u16*)b1h, (const u16*)b1l, (float*)h1p, 1);
    bn_stat<<<1, 256>>>(bng, bnb);
    tc_mlp2<<<tblocks, 512, SM_MLP2>>>(lng, lnb, out_x);
    tc256<<<tblocks, 512, SM_TC256>>>(out_x, (const u16*)b3h, (const u16*)b3l, (float*)pqp, 0);
    edge_out<<<eblocks, 256>>>(be, lneg, lneb, out_e);
}

// round 8
// speedup vs baseline: 1.1243x; 1.1243x over previous
#include <cuda_runtime.h>
#include <cuda_bf16.h>
#include <math.h>
#include <stdint.h>

#define N_NODES 50000
#define N_EDGES 800000
#define DIM 128

typedef unsigned long long ull;
typedef unsigned short u16;

// ---------------- scratch ----------------
__device__ float g_h[(size_t)N_NODES * DIM];         // aggr + x  (gemm1 input)
__device__ float g_h1[(size_t)N_NODES * 256];        // h @ W1.T
__device__ float g_PQ[(size_t)N_NODES * 256];        // [P | Q] per node
__device__ float2 g_edge[(size_t)N_EDGES];           // sorted (src_as_float, ea)
__device__ int g_eid[(size_t)N_EDGES];               // sorted original edge id
__device__ int g_cnt[N_NODES];
__device__ int g_off[N_NODES];
__device__ int g_cur[N_NODES];
__device__ float g_bnsum[512];
__device__ float g_bnstat[512];
// pre-split bf16 weights, [k][n] layout, padded rows
__device__ __align__(16) u16 g_B1h[128 * 264], g_B1l[128 * 264];   // W1:  k<128, n<256, stride 264
__device__ __align__(16) u16 g_B3h[128 * 264], g_B3l[128 * 264];   // We-remap: k<128, n<256
__device__ __align__(16) u16 g_B2h[256 * 136], g_B2l[256 * 136];   // W2:  k<256, n<128, stride 136

// ---------------- mma helpers ----------------
__device__ __forceinline__ uint32_t smem_u32(const void* p) {
    uint32_t a;
    asm("{ .reg .u64 t; cvta.to.shared.u64 t, %1; cvt.u32.u64 %0, t; }" : "=r"(a) : "l"(p));
    return a;
}
__device__ __forceinline__ void ldmx4(uint32_t* r, uint32_t addr) {
    asm volatile("ldmatrix.sync.aligned.m8n8.x4.shared.b16 {%0,%1,%2,%3}, [%4];"
        : "=r"(r[0]), "=r"(r[1]), "=r"(r[2]), "=r"(r[3]) : "r"(addr));
}
__device__ __forceinline__ void ldmx4t(uint32_t* r, uint32_t addr) {
    asm volatile("ldmatrix.sync.aligned.m8n8.x4.trans.shared.b16 {%0,%1,%2,%3}, [%4];"
        : "=r"(r[0]), "=r"(r[1]), "=r"(r[2]), "=r"(r[3]) : "r"(addr));
}
__device__ __forceinline__ void mma16816(float* c, const uint32_t* a, uint32_t b0, uint32_t b1) {
    asm volatile("mma.sync.aligned.m16n8k16.row.col.f32.bf16.bf16.f32 "
        "{%0,%1,%2,%3}, {%4,%5,%6,%7}, {%8,%9}, {%0,%1,%2,%3};"
        : "+f"(c[0]), "+f"(c[1]), "+f"(c[2]), "+f"(c[3])
        : "r"(a[0]), "r"(a[1]), "r"(a[2]), "r"(a[3]), "r"(b0), "r"(b1));
}
__device__ __forceinline__ void split2(float a, float b, uint32_t& uh, uint32_t& ul) {
    __nv_bfloat16 h0 = __float2bfloat16_rn(a), h1 = __float2bfloat16_rn(b);
    float r0 = a - __bfloat162float(h0), r1 = b - __bfloat162float(h1);
    __nv_bfloat16 l0 = __float2bfloat16_rn(r0), l1 = __float2bfloat16_rn(r1);
    uh = (uint32_t)(*(u16*)&h0) | ((uint32_t)(*(u16*)&h1) << 16);
    ul = (uint32_t)(*(u16*)&l0) | ((uint32_t)(*(u16*)&l1) << 16);
}

// SMEM layout (bytes)
#define CTRL 4096
#define ASTR 272                       // A row stride: 128 bf16 + 8 pad
#define OFF_AH CTRL
#define OFF_AL (OFF_AH + 128 * ASTR)
#define OFF_BH (OFF_AL + 128 * ASTR)
#define SM_TC256 (OFF_BH + 2 * 67584)
#define SM_MLP2  (OFF_BH + 2 * 69632)

// ---------------- weight prep ----------------
__global__ void __launch_bounds__(256) prep_w256(
    const float* __restrict__ W, u16* __restrict__ Bh, u16* __restrict__ Bl, int mode)
{
    int i = blockIdx.x * 256 + threadIdx.x;
    if (i >= 256 * 128) return;
    int j = i >> 7, k = i & 127;
    float v = (mode == 0) ? W[j * 128 + k]
            : ((j < 128) ? W[j * 256 + k] : W[(j - 128) * 256 + 128 + k]);
    __nv_bfloat16 hb = __float2bfloat16_rn(v);
    float rr = v - __bfloat162float(hb);
    __nv_bfloat16 lb = __float2bfloat16_rn(rr);
    Bh[k * 264 + j] = *(u16*)&hb;
    Bl[k * 264 + j] = *(u16*)&lb;
}
__global__ void __launch_bounds__(256) prep_w2(const float* __restrict__ W)
{
    int i = blockIdx.x * 256 + threadIdx.x;
    if (i >= 128 * 256) return;
    int j = i >> 8, k = i & 255;
    float v = W[i];
    __nv_bfloat16 hb = __float2bfloat16_rn(v);
    float rr = v - __bfloat162float(hb);
    __nv_bfloat16 lb = __float2bfloat16_rn(rr);
    g_B2h[k * 136 + j] = *(u16*)&hb;
    g_B2l[k * 136 + j] = *(u16*)&lb;
}

// ---------------- edge sort: hist / scan / scatter ----------------
__global__ void __launch_bounds__(256) hist(const int* __restrict__ dst)
{
    int e = blockIdx.x * 256 + threadIdx.x;
    if (e < N_EDGES) atomicAdd(&g_cnt[dst[e]], 1);
}

__global__ void __launch_bounds__(1024) scan50k()
{
    __shared__ int wsum[32];
    __shared__ int sh_carry;
    int tid = threadIdx.x, lane = tid & 31, w = tid >> 5;
    if (tid == 0) sh_carry = 0;
    __syncthreads();
    for (int base = 0; base < N_NODES; base += 1024) {
        int i = base + tid;
        int v = (i < N_NODES) ? g_cnt[i] : 0;
        int x = v;
#pragma unroll
        for (int o = 1; o < 32; o <<= 1) { int y = __shfl_up_sync(~0u, x, o); if (lane >= o) x += y; }
        if (lane == 31) wsum[w] = x;
        __syncthreads();
        if (w == 0) {
            int s = wsum[lane];
#pragma unroll
            for (int o = 1; o < 32; o <<= 1) { int y = __shfl_up_sync(~0u, s, o); if (lane >= o) s += y; }
            wsum[lane] = s;
        }
        __syncthreads();
        int warp_excl = (w == 0) ? 0 : wsum[w - 1];
        int carry = sh_carry;
        int excl = carry + warp_excl + x - v;
        if (i < N_NODES) { g_off[i] = excl; g_cur[i] = excl; }
        __syncthreads();
        if (tid == 1023) sh_carry = carry + wsum[31];
        __syncthreads();
    }
}

__global__ void __launch_bounds__(256) scatter(
    const int* __restrict__ src, const int* __restrict__ dst, const float* __restrict__ ea)
{
    int e = blockIdx.x * 256 + threadIdx.x;
    if (e >= N_EDGES) return;
    int d = dst[e];
    int pos = atomicAdd(&g_cur[d], 1);
    g_edge[pos] = make_float2(__int_as_float(src[e]), ea[e]);
    g_eid[pos] = e;
}

// ---------------- aggregate: warp per node -> g_h = softmax-aggr + x ----------------
__global__ void __launch_bounds__(256) aggregate(
    const float* __restrict__ x, const float* __restrict__ W_edge, const float* __restrict__ tptr)
{
    int gw = (blockIdx.x * 256 + threadIdx.x) >> 5;
    int lane = threadIdx.x & 31;
    if (gw >= N_NODES) return;
    const float t = tptr[0];
    float4 w4 = *(const float4*)&W_edge[lane * 4];

    int beg = g_off[gw];
    int end = (gw == N_NODES - 1) ? N_EDGES : g_off[gw + 1];

    float4 aE = make_float4(0.f, 0.f, 0.f, 0.f);
    float4 aM = make_float4(0.f, 0.f, 0.f, 0.f);

    for (int b = beg; b < end; b += 32) {
        int j = b + lane;
        float2 ed = (j < end) ? g_edge[j] : make_float2(0.f, 0.f);
        int cnt = min(32, end - b);
        for (int q = 0; q < cnt; q++) {
            int s   = __shfl_sync(0xffffffffu, __float_as_int(ed.x), q);
            float a = __shfl_sync(0xffffffffu, ed.y, q);
            float4 xv = *(const float4*)&x[(size_t)s * DIM + lane * 4];
            float m0 = fmaxf(fmaf(a, w4.x, xv.x), 0.f) + 1e-7f;
            float m1 = fmaxf(fmaf(a, w4.y, xv.y), 0.f) + 1e-7f;
            float m2 = fmaxf(fmaf(a, w4.z, xv.z), 0.f) + 1e-7f;
            float m3 = fmaxf(fmaf(a, w4.w, xv.w), 0.f) + 1e-7f;
            float e0 = __expf(m0 * t), e1 = __expf(m1 * t);
            float e2 = __expf(m2 * t), e3 = __expf(m3 * t);
            aE.x += e0; aE.y += e1; aE.z += e2; aE.w += e3;
            aM.x = fmaf(m0, e0, aM.x); aM.y = fmaf(m1, e1, aM.y);
            aM.z = fmaf(m2, e2, aM.z); aM.w = fmaf(m3, e3, aM.w);
        }
    }
    float4 xn = *(const float4*)&x[(size_t)gw * DIM + lane * 4];
    float4 h;
    h.x = aM.x / (aE.x + 1e-16f) + xn.x;
    h.y = aM.y / (aE.y + 1e-16f) + xn.y;
    h.z = aM.z / (aE.z + 1e-16f) + xn.z;
    h.w = aM.w / (aE.w + 1e-16f) + xn.w;
    *(float4*)&g_h[(size_t)gw * DIM + lane * 4] = h;
}

// ============================================================================
// tc256: out[rows x 256] = in[rows x 128] @ B[256 x 128]^T via mma.sync bf16 split
// ============================================================================
__global__ void __launch_bounds__(512, 1) tc256(
    const float* __restrict__ in, const u16* __restrict__ Bh, const u16* __restrict__ Bl,
    float* __restrict__ out)
{
    extern __shared__ __align__(16) char sm[];
    uint32_t sb = smem_u32(sm);
    int tid = threadIdx.x, wid = tid >> 5, lane = tid & 31;
    int row0 = blockIdx.x * 128;

    {
        const float4* bh = (const float4*)Bh;
        const float4* bl = (const float4*)Bl;
        float4* sh = (float4*)(sm + OFF_BH);
        float4* sl = (float4*)(sm + OFF_BH + 67584);
        for (int i = tid; i < 4224; i += 512) { sh[i] = bh[i]; sl[i] = bl[i]; }
    }
    for (int i = tid; i < 128 * 64; i += 512) {
        int r = i >> 6, k2 = (i & 63) << 1;
        int row = row0 + r;
        float2 hv = make_float2(0.f, 0.f);
        if (row < N_NODES) hv = *(const float2*)&in[(size_t)row * 128 + k2];
        uint32_t uh, ul;
        split2(hv.x, hv.y, uh, ul);
        *(uint32_t*)(sm + OFF_AH + r * ASTR + k2 * 2) = uh;
        *(uint32_t*)(sm + OFF_AL + r * ASTR + k2 * 2) = ul;
    }
    __syncthreads();

    int mrow0 = (wid & 7) * 16, nh = wid >> 3;
    uint32_t aRow = mrow0 + (lane & 7) + ((lane >> 3) & 1) * 8;
    uint32_t aAddrH = sb + OFF_AH + aRow * ASTR + (lane >> 4) * 16;
    uint32_t aAddrL = aAddrH + (OFF_AL - OFF_AH);
    uint32_t bLaneRow = (lane & 7) + ((lane >> 3) & 1) * 8;
    uint32_t bLaneN = ((lane >> 4) & 1) * 16 + nh * 256;

    float c[16][4];
#pragma unroll
    for (int t = 0; t < 16; t++)
#pragma unroll
        for (int q = 0; q < 4; q++) c[t][q] = 0.f;

#pragma unroll
    for (int kst = 0; kst < 8; kst++) {
        uint32_t ah[4], al[4];
        ldmx4(ah, aAddrH + kst * 32);
        ldmx4(al, aAddrL + kst * 32);
        uint32_t bAddr = sb + OFF_BH + (kst * 16 + bLaneRow) * 528 + bLaneN;
#pragma unroll
        for (int tp = 0; tp < 8; tp++) {
            uint32_t bh[4], bl[4];
            ldmx4t(bh, bAddr + tp * 32);
            ldmx4t(bl, bAddr + tp * 32 + 67584);
            mma16816(c[2 * tp],     ah, bh[0], bh[1]);
            mma16816(c[2 * tp],     al, bh[0], bh[1]);
            mma16816(c[2 * tp],     ah, bl[0], bl[1]);
            mma16816(c[2 * tp + 1], ah, bh[2], bh[3]);
            mma16816(c[2 * tp + 1], al, bh[2], bh[3]);
            mma16816(c[2 * tp + 1], ah, bl[2], bl[3]);
        }
    }

    int rbase = row0 + mrow0 + (lane >> 2);
    int cbase = nh * 128 + (lane & 3) * 2;
#pragma unroll
    for (int t = 0; t < 16; t++) {
        int n0 = cbase + t * 8;
        if (rbase < N_NODES)     *(float2*)&out[(size_t)rbase * 256 + n0]       = make_float2(c[t][0], c[t][1]);
        if (rbase + 8 < N_NODES) *(float2*)&out[(size_t)(rbase + 8) * 256 + n0] = make_float2(c[t][2], c[t][3]);
    }
}

// ---------------- bn column reduction over g_h1 ----------------
__global__ void __launch_bounds__(256) bn_reduce()
{
    int t = threadIdx.x;
    int r0 = blockIdx.x * 250, r1 = min(r0 + 250, N_NODES);
    float s = 0.f, q = 0.f;
    for (int row = r0; row < r1; row++) {
        float v = g_h1[(size_t)row * 256 + t];
        s += v; q += v * v;
    }
    atomicAdd(&g_bnsum[t], s);
    atomicAdd(&g_bnsum[256 + t], q);
}

__global__ void bn_stat(const float* __restrict__ bng, const float* __restrict__ bnb)
{
    int j = threadIdx.x;
    float s = g_bnsum[j], s2 = g_bnsum[256 + j];
    float mu = s * (1.0f / N_NODES);
    float var = s2 * (1.0f / N_NODES) - mu * mu;
    float rstd = rsqrtf(var + 1e-5f);
    float sc = rstd * bng[j];
    g_bnstat[j] = sc;
    g_bnstat[256 + j] = bnb[j] - mu * sc;
}

__device__ __forceinline__ float elu1(float v) { return v > 0.f ? v : expm1f(v); }

// ============================================================================
// tc_mlp2: out_x = ELU(LN(relu(bn(g_h1)) @ W2.T))
// ============================================================================
__global__ void __launch_bounds__(512, 1) tc_mlp2(
    const float* __restrict__ lng, const float* __restrict__ lnb, float* __restrict__ out_x)
{
    extern __shared__ __align__(16) char sm[];
    uint32_t sb = smem_u32(sm);
    int tid = threadIdx.x, wid = tid >> 5, lane = tid & 31;
    int row0 = blockIdx.x * 128;

    float* red  = (float*)sm;            // [128][4]
    float* lngs = (float*)(sm + 2048);
    float* lnbs = (float*)(sm + 2560);
    if (tid < 128) { lngs[tid] = lng[tid]; lnbs[tid] = lnb[tid]; }

    {
        const float4* bh = (const float4*)g_B2h;
        const float4* bl = (const float4*)g_B2l;
        float4* sh = (float4*)(sm + OFF_BH);
        float4* sl = (float4*)(sm + OFF_BH + 69632);
        for (int i = tid; i < 4352; i += 512) { sh[i] = bh[i]; sl[i] = bl[i]; }
    }

    int mrow0 = (wid & 7) * 16, nh = wid >> 3;
    uint32_t aRow = mrow0 + (lane & 7) + ((lane >> 3) & 1) * 8;
    uint32_t aAddrH = sb + OFF_AH + aRow * ASTR + (lane >> 4) * 16;
    uint32_t aAddrL = aAddrH + (OFF_AL - OFF_AH);
    uint32_t bLaneRow = (lane & 7) + ((lane >> 3) & 1) * 8;
    uint32_t bLaneN = ((lane >> 4) & 1) * 16 + nh * 128;

    float c[8][4];
#pragma unroll
    for (int t = 0; t < 8; t++)
#pragma unroll
        for (int q = 0; q < 4; q++) c[t][q] = 0.f;

#pragma unroll
    for (int s = 0; s < 2; s++) {
        __syncthreads();
        for (int i = tid; i < 128 * 64; i += 512) {
            int r = i >> 6, k2 = (i & 63) << 1;
            int row = row0 + r;
            float v0 = 0.f, v1 = 0.f;
            if (row < N_NODES) {
                int kc = s * 128 + k2;
                float2 hv = *(const float2*)&g_h1[(size_t)row * 256 + kc];
                v0 = fmaxf(fmaf(hv.x, g_bnstat[kc],     g_bnstat[256 + kc]),     0.f);
                v1 = fmaxf(fmaf(hv.y, g_bnstat[kc + 1], g_bnstat[256 + kc + 1]), 0.f);
            }
            uint32_t uh, ul;
            split2(v0, v1, uh, ul);
            *(uint32_t*)(sm + OFF_AH + r * ASTR + k2 * 2) = uh;
            *(uint32_t*)(sm + OFF_AL + r * ASTR + k2 * 2) = ul;
        }
        __syncthreads();

#pragma unroll
        for (int kst = 0; kst < 8; kst++) {
            uint32_t ah[4], al[4];
            ldmx4(ah, aAddrH + kst * 32);
            ldmx4(al, aAddrL + kst * 32);
            uint32_t bAddr = sb + OFF_BH + (s * 128 + kst * 16 + bLaneRow) * 272 + bLaneN;
#pragma unroll
            for (int tp = 0; tp < 4; tp++) {
                uint32_t bh[4], bl[4];
                ldmx4t(bh, bAddr + tp * 32);
                ldmx4t(bl, bAddr + tp * 32 + 69632);
                mma16816(c[2 * tp],     ah, bh[0], bh[1]);
                mma16816(c[2 * tp],     al, bh[0], bh[1]);
                mma16816(c[2 * tp],     ah, bl[0], bl[1]);
                mma16816(c[2 * tp + 1], ah, bh[2], bh[3]);
                mma16816(c[2 * tp + 1], al, bh[2], bh[3]);
                mma16816(c[2 * tp + 1], ah, bl[2], bl[3]);
            }
        }
    }

    float s1a = 0.f, s2a = 0.f, s1b = 0.f, s2b = 0.f;
#pragma unroll
    for (int t = 0; t < 8; t++) {
        s1a += c[t][0] + c[t][1];
        s2a += c[t][0] * c[t][0] + c[t][1] * c[t][1];
        s1b += c[t][2] + c[t][3];
        s2b += c[t][2] * c[t][2] + c[t][3] * c[t][3];
    }
#pragma unroll
    for (int o = 1; o < 4; o <<= 1) {
        s1a += __shfl_xor_sync(~0u, s1a, o);
        s2a += __shfl_xor_sync(~0u, s2a, o);
        s1b += __shfl_xor_sync(~0u, s1b, o);
        s2b += __shfl_xor_sync(~0u, s2b, o);
    }
    __syncthreads();
    if ((lane & 3) == 0) {
        int r = mrow0 + (lane >> 2);
        red[r * 4 + nh * 2]           = s1a;
        red[r * 4 + nh * 2 + 1]       = s2a;
        red[(r + 8) * 4 + nh * 2]     = s1b;
        red[(r + 8) * 4 + nh * 2 + 1] = s2b;
    }
    __syncthreads();
    {
        int ra = mrow0 + (lane >> 2), rb = ra + 8;
        float mua = (red[ra * 4] + red[ra * 4 + 2]) * (1.f / 128.f);
        float vara = (red[ra * 4 + 1] + red[ra * 4 + 3]) * (1.f / 128.f) - mua * mua;
        float rsa = rsqrtf(vara + 1e-5f);
        float mub = (red[rb * 4] + red[rb * 4 + 2]) * (1.f / 128.f);
        float varb = (red[rb * 4 + 1] + red[rb * 4 + 3]) * (1.f / 128.f) - mub * mub;
        float rsb = rsqrtf(varb + 1e-5f);
        int rowa = row0 + ra, rowb = row0 + rb;
#pragma unroll
        for (int t = 0; t < 8; t++) {
            int col = nh * 64 + t * 8 + (lane & 3) * 2;
            if (rowa < N_NODES) {
                float2 o;
                o.x = elu1((c[t][0] - mua) * rsa * lngs[col]     + lnbs[col]);
                o.y = elu1((c[t][1] - mua) * rsa * lngs[col + 1] + lnbs[col + 1]);
                *(float2*)&out_x[(size_t)rowa * DIM + col] = o;
            }
            if (rowb < N_NODES) {
                float2 o;
                o.x = elu1((c[t][2] - mub) * rsb * lngs[col]     + lnbs[col]);
                o.y = elu1((c[t][3] - mub) * rsb * lngs[col + 1] + lnbs[col + 1]);
                *(float2*)&out_x[(size_t)rowb * DIM + col] = o;
            }
        }
    }
}

// ---------------- edge_out: warp per node; Q row + bias in registers ----------------
__global__ void __launch_bounds__(256) edge_out(
    const float* __restrict__ be, const float* __restrict__ lng, const float* __restrict__ lnb,
    float* __restrict__ out_e)
{
    int gw = (blockIdx.x * 256 + threadIdx.x) >> 5;   // node
    int lane = threadIdx.x & 31;
    if (gw >= N_NODES) return;
    int j0 = lane * 4;
    float4 gv = *(const float4*)(lng + j0);
    float4 bv = *(const float4*)(lnb + j0);
    float4 qb;
    {
        float4 bev = *(const float4*)(be + j0);
        float4 qv = *(const float4*)&g_PQ[(size_t)gw * 256 + 128 + j0];
        qb.x = qv.x + bev.x; qb.y = qv.y + bev.y;
        qb.z = qv.z + bev.z; qb.w = qv.w + bev.w;
    }
    int beg = g_off[gw];
    int end = (gw == N_NODES - 1) ? N_EDGES : g_off[gw + 1];

    for (int b = beg; b < end; b += 32) {
        int j = b + lane;
        int sl = (j < end) ? __float_as_int(g_edge[j].x) : 0;
        int el = (j < end) ? g_eid[j] : 0;
        int cnt = min(32, end - b);
        for (int q = 0; q < cnt; q++) {
            int s   = __shfl_sync(0xffffffffu, sl, q);
            int eid = __shfl_sync(0xffffffffu, el, q);
            float4 p = *(const float4*)&g_PQ[(size_t)s * 256 + j0];
            float v0 = p.x + qb.x, v1 = p.y + qb.y, v2 = p.z + qb.z, v3 = p.w + qb.w;
            float g0 = 0.5f * v0 * (1.f + erff(v0 * 0.70710678118654752f));
            float g1 = 0.5f * v1 * (1.f + erff(v1 * 0.70710678118654752f));
            float g2 = 0.5f * v2 * (1.f + erff(v2 * 0.70710678118654752f));
            float g3 = 0.5f * v3 * (1.f + erff(v3 * 0.70710678118654752f));
            float s1 = g0 + g1 + g2 + g3;
            float s2 = g0 * g0 + g1 * g1 + g2 * g2 + g3 * g3;
#pragma unroll
            for (int o = 16; o > 0; o >>= 1) {
                s1 += __shfl_xor_sync(0xffffffffu, s1, o);
                s2 += __shfl_xor_sync(0xffffffffu, s2, o);
            }
            float mu = s1 * (1.f / 128.f);
            float var = s2 * (1.f / 128.f) - mu * mu;
            float rstd = rsqrtf(var + 1e-5f);
            float4 o;
            o.x = (g0 - mu) * rstd * gv.x + bv.x;
            o.y = (g1 - mu) * rstd * gv.y + bv.y;
            o.z = (g2 - mu) * rstd * gv.z + bv.z;
            o.w = (g3 - mu) * rstd * gv.w + bv.w;
            *(float4*)(out_e + (size_t)eid * DIM + j0) = o;
        }
    }
}

// ---------------- launch ----------------
extern "C" void kernel_launch(void* const* d_in, const int* in_sizes, int n_in,
                              void* d_out, int out_size)
{
    const float* x      = (const float*)d_in[0];
    const int*   ei     = (const int*)  d_in[1];
    const float* ea     = (const float*)d_in[2];
    const float* W_edge = (const float*)d_in[3];
    const float* tptr   = (const float*)d_in[4];
    const float* W1     = (const float*)d_in[5];
    const float* bng    = (const float*)d_in[6];
    const float* bnb    = (const float*)d_in[7];
    const float* W2     = (const float*)d_in[8];
    const float* lng    = (const float*)d_in[9];
    const float* lnb    = (const float*)d_in[10];
    const float* We     = (const float*)d_in[11];
    const float* be     = (const float*)d_in[12];
    const float* lneg   = (const float*)d_in[13];
    const float* lneb   = (const float*)d_in[14];

    const int* src = ei;
    const int* dst = ei + N_EDGES;

    float* out_x = (float*)d_out;
    float* out_e = out_x + (size_t)N_NODES * DIM;

    void *cntp, *bnp, *b1h, *b1l, *b3h, *b3l, *ghp, *h1p, *pqp;
    cudaGetSymbolAddress(&cntp, g_cnt);
    cudaGetSymbolAddress(&bnp, g_bnsum);
    cudaGetSymbolAddress(&b1h, g_B1h); cudaGetSymbolAddress(&b1l, g_B1l);
    cudaGetSymbolAddress(&b3h, g_B3h); cudaGetSymbolAddress(&b3l, g_B3l);
    cudaGetSymbolAddress(&ghp, g_h);
    cudaGetSymbolAddress(&h1p, g_h1);
    cudaGetSymbolAddress(&pqp, g_PQ);
    cudaMemsetAsync(cntp, 0, sizeof(int) * N_NODES, 0);
    cudaMemsetAsync(bnp, 0, sizeof(float) * 512, 0);

    cudaFuncSetAttribute(tc256, cudaFuncAttributeMaxDynamicSharedMemorySize, SM_TC256);
    cudaFuncSetAttribute(tc_mlp2, cudaFuncAttributeMaxDynamicSharedMemorySize, SM_MLP2);

    int eblocks256 = (N_EDGES + 255) / 256;
    int ablocks = (N_NODES * 32 + 255) / 256;
    int tblocks = (N_NODES + 127) / 128;

    prep_w256<<<128, 256>>>(W1, (u16*)b1h, (u16*)b1l, 0);
    prep_w256<<<128, 256>>>(We, (u16*)b3h, (u16*)b3l, 1);
    prep_w2<<<128, 256>>>(W2);

    hist<<<eblocks256, 256>>>(dst);
    scan50k<<<1, 1024>>>();
    scatter<<<eblocks256, 256>>>(src, dst, ea);
    aggregate<<<ablocks, 256>>>(x, W_edge, tptr);

    tc256<<<tblocks, 512, SM_TC256>>>((const float*)ghp, (const u16*)b1h, (const u16*)b1l, (float*)h1p);
    bn_reduce<<<200, 256>>>();
    bn_stat<<<1, 256>>>(bng, bnb);
    tc_mlp2<<<tblocks, 512, SM_MLP2>>>(lng, lnb, out_x);
    tc256<<<tblocks, 512, SM_TC256>>>(out_x, (const u16*)b3h, (const u16*)b3l, (float*)pqp);
    edge_out<<<ablocks, 256>>>(be, lneg, lneb, out_e);
}

// round 10
// speedup vs baseline: 1.1714x; 1.0420x over previous
#include <cuda_runtime.h>
#include <cuda_bf16.h>
#include <math.h>
#include <stdint.h>

#define N_NODES 50000
#define N_EDGES 800000
#define DIM 128

typedef unsigned long long ull;
typedef unsigned short u16;

// ---------------- scratch ----------------
__device__ float g_h[(size_t)N_NODES * DIM];         // aggr + x  (gemm1 input)
__device__ float g_h1[(size_t)N_NODES * 256];        // h @ W1.T
__device__ float g_PQ[(size_t)N_NODES * 256];        // [P | Q] per node
__device__ float4 g_edge[(size_t)N_EDGES];           // sorted (src_asf, ea, eid_asf, 0)
__device__ int g_cnt[N_NODES];
__device__ int g_off[N_NODES];
__device__ int g_cur[N_NODES];
__device__ float g_bnsum[512];
__device__ float g_bnstat[512];
// pre-split bf16 weights, [k][n] layout, padded rows
__device__ __align__(16) u16 g_B1h[128 * 264], g_B1l[128 * 264];   // W1:  k<128, n<256, stride 264
__device__ __align__(16) u16 g_B3h[128 * 264], g_B3l[128 * 264];   // We-remap: k<128, n<256
__device__ __align__(16) u16 g_B2h[256 * 136], g_B2l[256 * 136];   // W2:  k<256, n<128, stride 136

// ---------------- mma helpers ----------------
__device__ __forceinline__ uint32_t smem_u32(const void* p) {
    uint32_t a;
    asm("{ .reg .u64 t; cvta.to.shared.u64 t, %1; cvt.u32.u64 %0, t; }" : "=r"(a) : "l"(p));
    return a;
}
__device__ __forceinline__ void ldmx4(uint32_t* r, uint32_t addr) {
    asm volatile("ldmatrix.sync.aligned.m8n8.x4.shared.b16 {%0,%1,%2,%3}, [%4];"
        : "=r"(r[0]), "=r"(r[1]), "=r"(r[2]), "=r"(r[3]) : "r"(addr));
}
__device__ __forceinline__ void ldmx4t(uint32_t* r, uint32_t addr) {
    asm volatile("ldmatrix.sync.aligned.m8n8.x4.trans.shared.b16 {%0,%1,%2,%3}, [%4];"
        : "=r"(r[0]), "=r"(r[1]), "=r"(r[2]), "=r"(r[3]) : "r"(addr));
}
__device__ __forceinline__ void mma16816(float* c, const uint32_t* a, uint32_t b0, uint32_t b1) {
    asm volatile("mma.sync.aligned.m16n8k16.row.col.f32.bf16.bf16.f32 "
        "{%0,%1,%2,%3}, {%4,%5,%6,%7}, {%8,%9}, {%0,%1,%2,%3};"
        : "+f"(c[0]), "+f"(c[1]), "+f"(c[2]), "+f"(c[3])
        : "r"(a[0]), "r"(a[1]), "r"(a[2]), "r"(a[3]), "r"(b0), "r"(b1));
}
__device__ __forceinline__ void split2(float a, float b, uint32_t& uh, uint32_t& ul) {
    __nv_bfloat16 h0 = __float2bfloat16_rn(a), h1 = __float2bfloat16_rn(b);
    float r0 = a - __bfloat162float(h0), r1 = b - __bfloat162float(h1);
    __nv_bfloat16 l0 = __float2bfloat16_rn(r0), l1 = __float2bfloat16_rn(r1);
    uh = (uint32_t)(*(u16*)&h0) | ((uint32_t)(*(u16*)&h1) << 16);
    ul = (uint32_t)(*(u16*)&l0) | ((uint32_t)(*(u16*)&l1) << 16);
}

// SMEM layout (bytes)
#define CTRL 4096
#define ASTR 272                       // A row stride: 128 bf16 + 8 pad
#define OFF_AH CTRL
#define OFF_AL (OFF_AH + 128 * ASTR)
#define OFF_BH (OFF_AL + 128 * ASTR)   // 73728
#define SM_TC256 (OFF_BH + 2 * 67584)
#define SM_MLP2  (OFF_BH + 2 * 69632)  // 212992 (also holds B3 later: 2*67584)

// ---------------- weight prep (single kernel) ----------------
__global__ void __launch_bounds__(256) prep_all(
    const float* __restrict__ W1, const float* __restrict__ We, const float* __restrict__ W2)
{
    int b = blockIdx.x;
    int li = (b % 128) * 256 + threadIdx.x;
    if (b < 256) {   // W1 (b<128) or We (128<=b<256): out [k<128][n<256] stride 264
        int j = li >> 7, k = li & 127;
        float v = (b < 128) ? W1[j * 128 + k]
                : ((j < 128) ? We[j * 256 + k] : We[(j - 128) * 256 + 128 + k]);
        __nv_bfloat16 hb = __float2bfloat16_rn(v);
        float rr = v - __bfloat162float(hb);
        __nv_bfloat16 lb = __float2bfloat16_rn(rr);
        u16* Bh = (b < 128) ? g_B1h : g_B3h;
        u16* Bl = (b < 128) ? g_B1l : g_B3l;
        Bh[k * 264 + j] = *(u16*)&hb;
        Bl[k * 264 + j] = *(u16*)&lb;
    } else {         // W2: out [k<256][n<128] stride 136
        int j = li >> 8, k = li & 255;
        float v = W2[j * 256 + k];
        __nv_bfloat16 hb = __float2bfloat16_rn(v);
        float rr = v - __bfloat162float(hb);
        __nv_bfloat16 lb = __float2bfloat16_rn(rr);
        g_B2h[k * 136 + j] = *(u16*)&hb;
        g_B2l[k * 136 + j] = *(u16*)&lb;
    }
}

// ---------------- edge sort: hist / scan / scatter ----------------
__global__ void __launch_bounds__(256) hist(const int* __restrict__ dst)
{
    int e = blockIdx.x * 256 + threadIdx.x;
    if (e < N_EDGES) atomicAdd(&g_cnt[dst[e]], 1);
}

__global__ void __launch_bounds__(1024) scan50k()
{
    __shared__ int wsum[32];
    __shared__ int sh_carry;
    int tid = threadIdx.x, lane = tid & 31, w = tid >> 5;
    if (tid == 0) sh_carry = 0;
    __syncthreads();
    for (int base = 0; base < N_NODES; base += 1024) {
        int i = base + tid;
        int v = (i < N_NODES) ? g_cnt[i] : 0;
        int x = v;
#pragma unroll
        for (int o = 1; o < 32; o <<= 1) { int y = __shfl_up_sync(~0u, x, o); if (lane >= o) x += y; }
        if (lane == 31) wsum[w] = x;
        __syncthreads();
        if (w == 0) {
            int s = wsum[lane];
#pragma unroll
            for (int o = 1; o < 32; o <<= 1) { int y = __shfl_up_sync(~0u, s, o); if (lane >= o) s += y; }
            wsum[lane] = s;
        }
        __syncthreads();
        int warp_excl = (w == 0) ? 0 : wsum[w - 1];
        int carry = sh_carry;
        int excl = carry + warp_excl + x - v;
        if (i < N_NODES) { g_off[i] = excl; g_cur[i] = excl; }
        __syncthreads();
        if (tid == 1023) sh_carry = carry + wsum[31];
        __syncthreads();
    }
}

__global__ void __launch_bounds__(256) scatter(
    const int* __restrict__ src, const int* __restrict__ dst, const float* __restrict__ ea)
{
    int e = blockIdx.x * 256 + threadIdx.x;
    if (e >= N_EDGES) return;
    int d = dst[e];
    int pos = atomicAdd(&g_cur[d], 1);
    g_edge[pos] = make_float4(__int_as_float(src[e]), ea[e], __int_as_float(e), 0.f);
}

// ---------------- aggregate: warp per node -> g_h = softmax-aggr + x ----------------
__global__ void __launch_bounds__(256) aggregate(
    const float* __restrict__ x, const float* __restrict__ W_edge, const float* __restrict__ tptr)
{
    int gw = (blockIdx.x * 256 + threadIdx.x) >> 5;
    int lane = threadIdx.x & 31;
    if (gw >= N_NODES) return;
    const float t = tptr[0];
    float4 w4 = *(const float4*)&W_edge[lane * 4];

    int beg = g_off[gw];
    int end = (gw == N_NODES - 1) ? N_EDGES : g_off[gw + 1];

    float4 aE = make_float4(0.f, 0.f, 0.f, 0.f);
    float4 aM = make_float4(0.f, 0.f, 0.f, 0.f);

    for (int b = beg; b < end; b += 32) {
        int j = b + lane;
        float2 ed = make_float2(0.f, 0.f);
        if (j < end) { float4 e4 = g_edge[j]; ed = make_float2(e4.x, e4.y); }
        int cnt = min(32, end - b);
        for (int q = 0; q < cnt; q++) {
            int s   = __shfl_sync(0xffffffffu, __float_as_int(ed.x), q);
            float a = __shfl_sync(0xffffffffu, ed.y, q);
            float4 xv = *(const float4*)&x[(size_t)s * DIM + lane * 4];
            float m0 = fmaxf(fmaf(a, w4.x, xv.x), 0.f) + 1e-7f;
            float m1 = fmaxf(fmaf(a, w4.y, xv.y), 0.f) + 1e-7f;
            float m2 = fmaxf(fmaf(a, w4.z, xv.z), 0.f) + 1e-7f;
            float m3 = fmaxf(fmaf(a, w4.w, xv.w), 0.f) + 1e-7f;
            float e0 = __expf(m0 * t), e1 = __expf(m1 * t);
            float e2 = __expf(m2 * t), e3 = __expf(m3 * t);
            aE.x += e0; aE.y += e1; aE.z += e2; aE.w += e3;
            aM.x = fmaf(m0, e0, aM.x); aM.y = fmaf(m1, e1, aM.y);
            aM.z = fmaf(m2, e2, aM.z); aM.w = fmaf(m3, e3, aM.w);
        }
    }
    float4 xn = *(const float4*)&x[(size_t)gw * DIM + lane * 4];
    float4 h;
    h.x = aM.x / (aE.x + 1e-16f) + xn.x;
    h.y = aM.y / (aE.y + 1e-16f) + xn.y;
    h.z = aM.z / (aE.z + 1e-16f) + xn.z;
    h.w = aM.w / (aE.w + 1e-16f) + xn.w;
    *(float4*)&g_h[(size_t)gw * DIM + lane * 4] = h;
}

// ============================================================================
// tc256: g_h1[rows x 256] = g_h[rows x 128] @ W1[256 x 128]^T via mma.sync bf16 split
// ============================================================================
__global__ void __launch_bounds__(512, 1) tc256(
    const float* __restrict__ in, const u16* __restrict__ Bh, const u16* __restrict__ Bl,
    float* __restrict__ out)
{
    extern __shared__ __align__(16) char sm[];
    uint32_t sb = smem_u32(sm);
    int tid = threadIdx.x, wid = tid >> 5, lane = tid & 31;
    int row0 = blockIdx.x * 128;

    {
        const float4* bh = (const float4*)Bh;
        const float4* bl = (const float4*)Bl;
        float4* sh = (float4*)(sm + OFF_BH);
        float4* sl = (float4*)(sm + OFF_BH + 67584);
        for (int i = tid; i < 4224; i += 512) { sh[i] = bh[i]; sl[i] = bl[i]; }
    }
    for (int i = tid; i < 128 * 64; i += 512) {
        int r = i >> 6, k2 = (i & 63) << 1;
        int row = row0 + r;
        float2 hv = make_float2(0.f, 0.f);
        if (row < N_NODES) hv = *(const float2*)&in[(size_t)row * 128 + k2];
        uint32_t uh, ul;
        split2(hv.x, hv.y, uh, ul);
        *(uint32_t*)(sm + OFF_AH + r * ASTR + k2 * 2) = uh;
        *(uint32_t*)(sm + OFF_AL + r * ASTR + k2 * 2) = ul;
    }
    __syncthreads();

    int mrow0 = (wid & 7) * 16, nh = wid >> 3;
    uint32_t aRow = mrow0 + (lane & 7) + ((lane >> 3) & 1) * 8;
    uint32_t aAddrH = sb + OFF_AH + aRow * ASTR + (lane >> 4) * 16;
    uint32_t aAddrL = aAddrH + (OFF_AL - OFF_AH);
    uint32_t bLaneRow = (lane & 7) + ((lane >> 3) & 1) * 8;
    uint32_t bLaneN = ((lane >> 4) & 1) * 16 + nh * 256;

    float c[16][4];
#pragma unroll
    for (int t = 0; t < 16; t++)
#pragma unroll
        for (int q = 0; q < 4; q++) c[t][q] = 0.f;

#pragma unroll
    for (int kst = 0; kst < 8; kst++) {
        uint32_t ah[4], al[4];
        ldmx4(ah, aAddrH + kst * 32);
        ldmx4(al, aAddrL + kst * 32);
        uint32_t bAddr = sb + OFF_BH + (kst * 16 + bLaneRow) * 528 + bLaneN;
#pragma unroll
        for (int tp = 0; tp < 8; tp++) {
            uint32_t bh[4], bl[4];
            ldmx4t(bh, bAddr + tp * 32);
            ldmx4t(bl, bAddr + tp * 32 + 67584);
            mma16816(c[2 * tp],     ah, bh[0], bh[1]);
            mma16816(c[2 * tp],     al, bh[0], bh[1]);
            mma16816(c[2 * tp],     ah, bl[0], bl[1]);
            mma16816(c[2 * tp + 1], ah, bh[2], bh[3]);
            mma16816(c[2 * tp + 1], al, bh[2], bh[3]);
            mma16816(c[2 * tp + 1], ah, bl[2], bl[3]);
        }
    }

    int rbase = row0 + mrow0 + (lane >> 2);
    int cbase = nh * 128 + (lane & 3) * 2;
#pragma unroll
    for (int t = 0; t < 16; t++) {
        int n0 = cbase + t * 8;
        if (rbase < N_NODES)     *(float2*)&out[(size_t)rbase * 256 + n0]       = make_float2(c[t][0], c[t][1]);
        if (rbase + 8 < N_NODES) *(float2*)&out[(size_t)(rbase + 8) * 256 + n0] = make_float2(c[t][2], c[t][3]);
    }
}

// ---------------- bn column reduction over g_h1 ----------------
__global__ void __launch_bounds__(256) bn_reduce()
{
    int t = threadIdx.x;
    int r0 = blockIdx.x * 250, r1 = min(r0 + 250, N_NODES);
    float s = 0.f, q = 0.f;
    for (int row = r0; row < r1; row++) {
        float v = g_h1[(size_t)row * 256 + t];
        s += v; q += v * v;
    }
    atomicAdd(&g_bnsum[t], s);
    atomicAdd(&g_bnsum[256 + t], q);
}

__global__ void bn_stat(const float* __restrict__ bng, const float* __restrict__ bnb)
{
    int j = threadIdx.x;
    float s = g_bnsum[j], s2 = g_bnsum[256 + j];
    float mu = s * (1.0f / N_NODES);
    float var = s2 * (1.0f / N_NODES) - mu * mu;
    float rstd = rsqrtf(var + 1e-5f);
    float sc = rstd * bng[j];
    g_bnstat[j] = sc;
    g_bnstat[256 + j] = bnb[j] - mu * sc;
}

__device__ __forceinline__ float elu1(float v) { return v > 0.f ? v : expm1f(v); }

// ============================================================================
// tc_mlp2pq: out_x = ELU(LN(relu(bn(g_h1)) @ W2.T)); then PQ = out_x @ We' in-kernel
// ============================================================================
__global__ void __launch_bounds__(512, 1) tc_mlp2pq(
    const float* __restrict__ lng, const float* __restrict__ lnb, float* __restrict__ out_x)
{
    extern __shared__ __align__(16) char sm[];
    uint32_t sb = smem_u32(sm);
    int tid = threadIdx.x, wid = tid >> 5, lane = tid & 31;
    int row0 = blockIdx.x * 128;

    float* red  = (float*)sm;            // [128][4]
    float* lngs = (float*)(sm + 2048);
    float* lnbs = (float*)(sm + 2560);
    if (tid < 128) { lngs[tid] = lng[tid]; lnbs[tid] = lnb[tid]; }

    {
        const float4* bh = (const float4*)g_B2h;
        const float4* bl = (const float4*)g_B2l;
        float4* sh = (float4*)(sm + OFF_BH);
        float4* sl = (float4*)(sm + OFF_BH + 69632);
        for (int i = tid; i < 4352; i += 512) { sh[i] = bh[i]; sl[i] = bl[i]; }
    }

    int mrow0 = (wid & 7) * 16, nh = wid >> 3;
    uint32_t aRow = mrow0 + (lane & 7) + ((lane >> 3) & 1) * 8;
    uint32_t aAddrH = sb + OFF_AH + aRow * ASTR + (lane >> 4) * 16;
    uint32_t aAddrL = aAddrH + (OFF_AL - OFF_AH);
    uint32_t bLaneRow = (lane & 7) + ((lane >> 3) & 1) * 8;
    uint32_t bLaneN = ((lane >> 4) & 1) * 16 + nh * 128;

    float c[8][4];
#pragma unroll
    for (int t = 0; t < 8; t++)
#pragma unroll
        for (int q = 0; q < 4; q++) c[t][q] = 0.f;

#pragma unroll
    for (int s = 0; s < 2; s++) {
        __syncthreads();
        for (int i = tid; i < 128 * 64; i += 512) {
            int r = i >> 6, k2 = (i & 63) << 1;
            int row = row0 + r;
            float v0 = 0.f, v1 = 0.f;
            if (row < N_NODES) {
                int kc = s * 128 + k2;
                float2 hv = *(const float2*)&g_h1[(size_t)row * 256 + kc];
                v0 = fmaxf(fmaf(hv.x, g_bnstat[kc],     g_bnstat[256 + kc]),     0.f);
                v1 = fmaxf(fmaf(hv.y, g_bnstat[kc + 1], g_bnstat[256 + kc + 1]), 0.f);
            }
            uint32_t uh, ul;
            split2(v0, v1, uh, ul);
            *(uint32_t*)(sm + OFF_AH + r * ASTR + k2 * 2) = uh;
            *(uint32_t*)(sm + OFF_AL + r * ASTR + k2 * 2) = ul;
        }
        __syncthreads();

#pragma unroll
        for (int kst = 0; kst < 8; kst++) {
            uint32_t ah[4], al[4];
            ldmx4(ah, aAddrH + kst * 32);
            ldmx4(al, aAddrL + kst * 32);
            uint32_t bAddr = sb + OFF_BH + (s * 128 + kst * 16 + bLaneRow) * 272 + bLaneN;
#pragma unroll
            for (int tp = 0; tp < 4; tp++) {
                uint32_t bh[4], bl[4];
                ldmx4t(bh, bAddr + tp * 32);
                ldmx4t(bl, bAddr + tp * 32 + 69632);
                mma16816(c[2 * tp],     ah, bh[0], bh[1]);
                mma16816(c[2 * tp],     al, bh[0], bh[1]);
                mma16816(c[2 * tp],     ah, bl[0], bl[1]);
                mma16816(c[2 * tp + 1], ah, bh[2], bh[3]);
                mma16816(c[2 * tp + 1], al, bh[2], bh[3]);
                mma16816(c[2 * tp + 1], ah, bl[2], bl[3]);
            }
        }
    }

    // ---- barrier: everyone done reading B2, start loading B3 over it ----
    __syncthreads();
    {
        const float4* bh = (const float4*)g_B3h;
        const float4* bl = (const float4*)g_B3l;
        float4* sh = (float4*)(sm + OFF_BH);
        float4* sl = (float4*)(sm + OFF_BH + 67584);
        for (int i = tid; i < 4224; i += 512) { sh[i] = bh[i]; sl[i] = bl[i]; }
    }

    // ---- LN + ELU epilogue; write out_x AND bf16-split into A smem ----
    float s1a = 0.f, s2a = 0.f, s1b = 0.f, s2b = 0.f;
#pragma unroll
    for (int t = 0; t < 8; t++) {
        s1a += c[t][0] + c[t][1];
        s2a += c[t][0] * c[t][0] + c[t][1] * c[t][1];
        s1b += c[t][2] + c[t][3];
        s2b += c[t][2] * c[t][2] + c[t][3] * c[t][3];
    }
#pragma unroll
    for (int o = 1; o < 4; o <<= 1) {
        s1a += __shfl_xor_sync(~0u, s1a, o);
        s2a += __shfl_xor_sync(~0u, s2a, o);
        s1b += __shfl_xor_sync(~0u, s1b, o);
        s2b += __shfl_xor_sync(~0u, s2b, o);
    }
    __syncthreads();
    if ((lane & 3) == 0) {
        int r = mrow0 + (lane >> 2);
        red[r * 4 + nh * 2]           = s1a;
        red[r * 4 + nh * 2 + 1]       = s2a;
        red[(r + 8) * 4 + nh * 2]     = s1b;
        red[(r + 8) * 4 + nh * 2 + 1] = s2b;
    }
    __syncthreads();
    {
        int ra = mrow0 + (lane >> 2), rb = ra + 8;
        float mua = (red[ra * 4] + red[ra * 4 + 2]) * (1.f / 128.f);
        float vara = (red[ra * 4 + 1] + red[ra * 4 + 3]) * (1.f / 128.f) - mua * mua;
        float rsa = rsqrtf(vara + 1e-5f);
        float mub = (red[rb * 4] + red[rb * 4 + 2]) * (1.f / 128.f);
        float varb = (red[rb * 4 + 1] + red[rb * 4 + 3]) * (1.f / 128.f) - mub * mub;
        float rsb = rsqrtf(varb + 1e-5f);
        int rowa = row0 + ra, rowb = row0 + rb;
#pragma unroll
        for (int t = 0; t < 8; t++) {
            int col = nh * 64 + t * 8 + (lane & 3) * 2;
            float oax = elu1((c[t][0] - mua) * rsa * lngs[col]     + lnbs[col]);
            float oay = elu1((c[t][1] - mua) * rsa * lngs[col + 1] + lnbs[col + 1]);
            float obx = elu1((c[t][2] - mub) * rsb * lngs[col]     + lnbs[col]);
            float oby = elu1((c[t][3] - mub) * rsb * lngs[col + 1] + lnbs[col + 1]);
            if (rowa < N_NODES) *(float2*)&out_x[(size_t)rowa * DIM + col] = make_float2(oax, oay);
            if (rowb < N_NODES) *(float2*)&out_x[(size_t)rowb * DIM + col] = make_float2(obx, oby);
            uint32_t uh, ul;
            split2(oax, oay, uh, ul);
            *(uint32_t*)(sm + OFF_AH + ra * ASTR + col * 2) = uh;
            *(uint32_t*)(sm + OFF_AL + ra * ASTR + col * 2) = ul;
            split2(obx, oby, uh, ul);
            *(uint32_t*)(sm + OFF_AH + rb * ASTR + col * 2) = uh;
            *(uint32_t*)(sm + OFF_AL + rb * ASTR + col * 2) = ul;
        }
    }
    __syncthreads();

    // ---- second MMA: PQ = out_x @ [WeL|WeR]^T (out 256 cols) ----
    uint32_t bLaneN2 = ((lane >> 4) & 1) * 16 + nh * 256;
    float c2[16][4];
#pragma unroll
    for (int t = 0; t < 16; t++)
#pragma unroll
        for (int q = 0; q < 4; q++) c2[t][q] = 0.f;

#pragma unroll
    for (int kst = 0; kst < 8; kst++) {
        uint32_t ah[4], al[4];
        ldmx4(ah, aAddrH + kst * 32);
        ldmx4(al, aAddrL + kst * 32);
        uint32_t bAddr = sb + OFF_BH + (kst * 16 + bLaneRow) * 528 + bLaneN2;
#pragma unroll
        for (int tp = 0; tp < 8; tp++) {
            uint32_t bh[4], bl[4];
            ldmx4t(bh, bAddr + tp * 32);
            ldmx4t(bl, bAddr + tp * 32 + 67584);
            mma16816(c2[2 * tp],     ah, bh[0], bh[1]);
            mma16816(c2[2 * tp],     al, bh[0], bh[1]);
            mma16816(c2[2 * tp],     ah, bl[0], bl[1]);
            mma16816(c2[2 * tp + 1], ah, bh[2], bh[3]);
            mma16816(c2[2 * tp + 1], al, bh[2], bh[3]);
            mma16816(c2[2 * tp + 1], ah, bl[2], bl[3]);
        }
    }

    int rbase = row0 + mrow0 + (lane >> 2);
    int cbase = nh * 128 + (lane & 3) * 2;
#pragma unroll
    for (int t = 0; t < 16; t++) {
        int n0 = cbase + t * 8;
        if (rbase < N_NODES)     *(float2*)&g_PQ[(size_t)rbase * 256 + n0]       = make_float2(c2[t][0], c2[t][1]);
        if (rbase + 8 < N_NODES) *(float2*)&g_PQ[(size_t)(rbase + 8) * 256 + n0] = make_float2(c2[t][2], c2[t][3]);
    }
}

// ---------------- edge_out: warp per node; Q row + bias in registers ----------------
__global__ void __launch_bounds__(256) edge_out(
    const float* __restrict__ be, const float* __restrict__ lng, const float* __restrict__ lnb,
    float* __restrict__ out_e)
{
    int gw = (blockIdx.x * 256 + threadIdx.x) >> 5;   // node
    int lane = threadIdx.x & 31;
    if (gw >= N_NODES) return;
    int j0 = lane * 4;
    float4 gv = *(const float4*)(lng + j0);
    float4 bv = *(const float4*)(lnb + j0);
    float4 qb;
    {
        float4 bev = *(const float4*)(be + j0);
        float4 qv = *(const float4*)&g_PQ[(size_t)gw * 256 + 128 + j0];
        qb.x = qv.x + bev.x; qb.y = qv.y + bev.y;
        qb.z = qv.z + bev.z; qb.w = qv.w + bev.w;
    }
    int beg = g_off[gw];
    int end = (gw == N_NODES - 1) ? N_EDGES : g_off[gw + 1];

    for (int b = beg; b < end; b += 32) {
        int j = b + lane;
        int sl = 0, el = 0;
        if (j < end) { float4 e4 = g_edge[j]; sl = __float_as_int(e4.x); el = __float_as_int(e4.z); }
        int cnt = min(32, end - b);
        for (int q = 0; q < cnt; q++) {
            int s   = __shfl_sync(0xffffffffu, sl, q);
            int eid = __shfl_sync(0xffffffffu, el, q);
            float4 p = *(const float4*)&g_PQ[(size_t)s * 256 + j0];
            float v0 = p.x + qb.x, v1 = p.y + qb.y, v2 = p.z + qb.z, v3 = p.w + qb.w;
            float g0 = 0.5f * v0 * (1.f + erff(v0 * 0.70710678118654752f));
            float g1 = 0.5f * v1 * (1.f + erff(v1 * 0.70710678118654752f));
            float g2 = 0.5f * v2 * (1.f + erff(v2 * 0.70710678118654752f));
            float g3 = 0.5f * v3 * (1.f + erff(v3 * 0.70710678118654752f));
            float s1 = g0 + g1 + g2 + g3;
            float s2 = g0 * g0 + g1 * g1 + g2 * g2 + g3 * g3;
#pragma unroll
            for (int o = 16; o > 0; o >>= 1) {
                s1 += __shfl_xor_sync(0xffffffffu, s1, o);
                s2 += __shfl_xor_sync(0xffffffffu, s2, o);
            }
            float mu = s1 * (1.f / 128.f);
            float var = s2 * (1.f / 128.f) - mu * mu;
            float rstd = rsqrtf(var + 1e-5f);
            float4 o;
            o.x = (g0 - mu) * rstd * gv.x + bv.x;
            o.y = (g1 - mu) * rstd * gv.y + bv.y;
            o.z = (g2 - mu) * rstd * gv.z + bv.z;
            o.w = (g3 - mu) * rstd * gv.w + bv.w;
            *(float4*)(out_e + (size_t)eid * DIM + j0) = o;
        }
    }
}

// ---------------- launch ----------------
extern "C" void kernel_launch(void* const* d_in, const int* in_sizes, int n_in,
                              void* d_out, int out_size)
{
    const float* x      = (const float*)d_in[0];
    const int*   ei     = (const int*)  d_in[1];
    const float* ea     = (const float*)d_in[2];
    const float* W_edge = (const float*)d_in[3];
    const float* tptr   = (const float*)d_in[4];
    const float* W1     = (const float*)d_in[5];
    const float* bng    = (const float*)d_in[6];
    const float* bnb    = (const float*)d_in[7];
    const float* W2     = (const float*)d_in[8];
    const float* lng    = (const float*)d_in[9];
    const float* lnb    = (const float*)d_in[10];
    const float* We     = (const float*)d_in[11];
    const float* be     = (const float*)d_in[12];
    const float* lneg   = (const float*)d_in[13];
    const float* lneb   = (const float*)d_in[14];

    const int* src = ei;
    const int* dst = ei + N_EDGES;

    float* out_x = (float*)d_out;
    float* out_e = out_x + (size_t)N_NODES * DIM;

    void *cntp, *bnp, *b1h, *b1l, *ghp, *h1p;
    cudaGetSymbolAddress(&cntp, g_cnt);
    cudaGetSymbolAddress(&bnp, g_bnsum);
    cudaGetSymbolAddress(&b1h, g_B1h);
    cudaGetSymbolAddress(&b1l, g_B1l);
    cudaGetSymbolAddress(&ghp, g_h);
    cudaGetSymbolAddress(&h1p, g_h1);

    cudaFuncSetAttribute(tc256, cudaFuncAttributeMaxDynamicSharedMemorySize, SM_TC256);
    cudaFuncSetAttribute(tc_mlp2pq, cudaFuncAttributeMaxDynamicSharedMemorySize, SM_MLP2);

    int eblocks256 = (N_EDGES + 255) / 256;
    int ablocks = (N_NODES * 32 + 255) / 256;
    int tblocks = (N_NODES + 127) / 128;

    // launch order chosen so ncu (-s 5 -c 1) captures `aggregate`
    cudaMemsetAsync(cntp, 0, sizeof(int) * N_NODES, 0);          // 1
    prep_all<<<384, 256>>>(W1, We, W2);                          // 2
    hist<<<eblocks256, 256>>>(dst);                              // 3
    scan50k<<<1, 1024>>>();                                      // 4
    scatter<<<eblocks256, 256>>>(src, dst, ea);                  // 5
    aggregate<<<ablocks, 256>>>(x, W_edge, tptr);                // 6 <- profiled
    cudaMemsetAsync(bnp, 0, sizeof(float) * 512, 0);             // 7

    tc256<<<tblocks, 512, SM_TC256>>>((const float*)ghp, (const u16*)b1h, (const u16*)b1l, (float*)h1p);
    bn_reduce<<<200, 256>>>();
    bn_stat<<<1, 256>>>(bng, bnb);
    tc_mlp2pq<<<tblocks, 512, SM_MLP2>>>(lng, lnb, out_x);
    edge_out<<<ablocks, 256>>>(be, lneg, lneb, out_e);
}

// round 11
// speedup vs baseline: 1.1812x; 1.0083x over previous
#include <cuda_runtime.h>
#include <cuda_bf16.h>
#include <math.h>
#include <stdint.h>

#define N_NODES 50000
#define N_EDGES 800000
#define DIM 128

typedef unsigned long long ull;
typedef unsigned short u16;

// ---------------- scratch ----------------
__device__ float g_h[(size_t)N_NODES * DIM];         // aggr + x  (gemm1 input)
__device__ float g_h1[(size_t)N_NODES * 256];        // h @ W1.T
__device__ float g_PQ[(size_t)N_NODES * 256];        // [P | Q] per node
__device__ float4 g_edge[(size_t)N_EDGES];           // sorted (src_asf, ea, eid_asf, 0)
__device__ int g_cnt[N_NODES];
__device__ int g_off[N_NODES];
__device__ int g_cur[N_NODES];
__device__ float g_bnsum[512];
__device__ float g_bnstat[512];
// pre-split bf16 weights, [k][n] layout, padded rows
__device__ __align__(16) u16 g_B1h[128 * 264], g_B1l[128 * 264];   // W1:  k<128, n<256, stride 264
__device__ __align__(16) u16 g_B3h[128 * 264], g_B3l[128 * 264];   // We-remap: k<128, n<256
__device__ __align__(16) u16 g_B2h[256 * 136], g_B2l[256 * 136];   // W2:  k<256, n<128, stride 136

// ---------------- mma helpers ----------------
__device__ __forceinline__ uint32_t smem_u32(const void* p) {
    uint32_t a;
    asm("{ .reg .u64 t; cvta.to.shared.u64 t, %1; cvt.u32.u64 %0, t; }" : "=r"(a) : "l"(p));
    return a;
}
__device__ __forceinline__ void ldmx4(uint32_t* r, uint32_t addr) {
    asm volatile("ldmatrix.sync.aligned.m8n8.x4.shared.b16 {%0,%1,%2,%3}, [%4];"
        : "=r"(r[0]), "=r"(r[1]), "=r"(r[2]), "=r"(r[3]) : "r"(addr));
}
__device__ __forceinline__ void ldmx4t(uint32_t* r, uint32_t addr) {
    asm volatile("ldmatrix.sync.aligned.m8n8.x4.trans.shared.b16 {%0,%1,%2,%3}, [%4];"
        : "=r"(r[0]), "=r"(r[1]), "=r"(r[2]), "=r"(r[3]) : "r"(addr));
}
__device__ __forceinline__ void mma16816(float* c, const uint32_t* a, uint32_t b0, uint32_t b1) {
    asm volatile("mma.sync.aligned.m16n8k16.row.col.f32.bf16.bf16.f32 "
        "{%0,%1,%2,%3}, {%4,%5,%6,%7}, {%8,%9}, {%0,%1,%2,%3};"
        : "+f"(c[0]), "+f"(c[1]), "+f"(c[2]), "+f"(c[3])
        : "r"(a[0]), "r"(a[1]), "r"(a[2]), "r"(a[3]), "r"(b0), "r"(b1));
}
__device__ __forceinline__ void split2(float a, float b, uint32_t& uh, uint32_t& ul) {
    __nv_bfloat16 h0 = __float2bfloat16_rn(a), h1 = __float2bfloat16_rn(b);
    float r0 = a - __bfloat162float(h0), r1 = b - __bfloat162float(h1);
    __nv_bfloat16 l0 = __float2bfloat16_rn(r0), l1 = __float2bfloat16_rn(r1);
    uh = (uint32_t)(*(u16*)&h0) | ((uint32_t)(*(u16*)&h1) << 16);
    ul = (uint32_t)(*(u16*)&l0) | ((uint32_t)(*(u16*)&l1) << 16);
}

// SMEM layout (bytes)
#define CTRL 4096
#define ASTR 272                       // A row stride: 128 bf16 + 8 pad
#define OFF_AH CTRL
#define OFF_AL (OFF_AH + 128 * ASTR)
#define OFF_BH (OFF_AL + 128 * ASTR)   // 73728
#define SM_TC256 (OFF_BH + 2 * 67584)
#define SM_MLP2  (OFF_BH + 2 * 69632)  // 212992 (also holds B3 later: 2*67584)

// ---------------- weight prep + cnt zeroing (single kernel) ----------------
__global__ void __launch_bounds__(256) prep_all(
    const float* __restrict__ W1, const float* __restrict__ We, const float* __restrict__ W2)
{
    int b = blockIdx.x;
    if (b >= 384) {      // zero g_cnt
        int i = (b - 384) * 256 + threadIdx.x;
        if (i < N_NODES) g_cnt[i] = 0;
        return;
    }
    int li = (b % 128) * 256 + threadIdx.x;
    if (b < 256) {   // W1 (b<128) or We (128<=b<256): out [k<128][n<256] stride 264
        int j = li >> 7, k = li & 127;
        float v = (b < 128) ? W1[j * 128 + k]
                : ((j < 128) ? We[j * 256 + k] : We[(j - 128) * 256 + 128 + k]);
        __nv_bfloat16 hb = __float2bfloat16_rn(v);
        float rr = v - __bfloat162float(hb);
        __nv_bfloat16 lb = __float2bfloat16_rn(rr);
        u16* Bh = (b < 128) ? g_B1h : g_B3h;
        u16* Bl = (b < 128) ? g_B1l : g_B3l;
        Bh[k * 264 + j] = *(u16*)&hb;
        Bl[k * 264 + j] = *(u16*)&lb;
    } else {         // W2: out [k<256][n<128] stride 136
        int j = li >> 8, k = li & 255;
        float v = W2[j * 256 + k];
        __nv_bfloat16 hb = __float2bfloat16_rn(v);
        float rr = v - __bfloat162float(hb);
        __nv_bfloat16 lb = __float2bfloat16_rn(rr);
        g_B2h[k * 136 + j] = *(u16*)&hb;
        g_B2l[k * 136 + j] = *(u16*)&lb;
    }
}

// ---------------- edge sort: hist / scan / scatter ----------------
__global__ void __launch_bounds__(256) hist(const int* __restrict__ dst)
{
    int e = blockIdx.x * 256 + threadIdx.x;
    if (e < N_EDGES) atomicAdd(&g_cnt[dst[e]], 1);
}

__global__ void __launch_bounds__(1024) scan50k()
{
    __shared__ int wsum[32];
    __shared__ int sh_carry;
    int tid = threadIdx.x, lane = tid & 31, w = tid >> 5;
    if (tid == 0) sh_carry = 0;
    __syncthreads();
    for (int base = 0; base < N_NODES; base += 1024) {
        int i = base + tid;
        int v = (i < N_NODES) ? g_cnt[i] : 0;
        int x = v;
#pragma unroll
        for (int o = 1; o < 32; o <<= 1) { int y = __shfl_up_sync(~0u, x, o); if (lane >= o) x += y; }
        if (lane == 31) wsum[w] = x;
        __syncthreads();
        if (w == 0) {
            int s = wsum[lane];
#pragma unroll
            for (int o = 1; o < 32; o <<= 1) { int y = __shfl_up_sync(~0u, s, o); if (lane >= o) s += y; }
            wsum[lane] = s;
        }
        __syncthreads();
        int warp_excl = (w == 0) ? 0 : wsum[w - 1];
        int carry = sh_carry;
        int excl = carry + warp_excl + x - v;
        if (i < N_NODES) { g_off[i] = excl; g_cur[i] = excl; }
        __syncthreads();
        if (tid == 1023) sh_carry = carry + wsum[31];
        __syncthreads();
    }
}

__global__ void __launch_bounds__(256) scatter(
    const int* __restrict__ src, const int* __restrict__ dst, const float* __restrict__ ea)
{
    int e = blockIdx.x * 256 + threadIdx.x;
    if (e >= N_EDGES) return;
    int d = dst[e];
    int pos = atomicAdd(&g_cur[d], 1);
    g_edge[pos] = make_float4(__int_as_float(src[e]), ea[e], __int_as_float(e), 0.f);
}

// ---------------- aggregate: warp per node, prefetched gather ----------------
__global__ void __launch_bounds__(256) aggregate(
    const float* __restrict__ x, const float* __restrict__ W_edge, const float* __restrict__ tptr)
{
    int gw = (blockIdx.x * 256 + threadIdx.x) >> 5;
    int lane = threadIdx.x & 31;
    if (gw >= N_NODES) return;
    const float t = tptr[0];
    float4 w4 = *(const float4*)&W_edge[lane * 4];

    int beg = g_off[gw];
    int end = (gw == N_NODES - 1) ? N_EDGES : g_off[gw + 1];

    float4 aE = make_float4(0.f, 0.f, 0.f, 0.f);
    float4 aM = make_float4(0.f, 0.f, 0.f, 0.f);

    for (int b = beg; b < end; b += 32) {
        int j = b + lane;
        float2 ed = make_float2(0.f, 0.f);
        if (j < end) { float4 e4 = g_edge[j]; ed = make_float2(e4.x, e4.y); }
        int cnt = min(32, end - b);
        // prefetch first
        int s_cur = __shfl_sync(0xffffffffu, __float_as_int(ed.x), 0);
        float a_cur = __shfl_sync(0xffffffffu, ed.y, 0);
        float4 xv = *(const float4*)&x[(size_t)s_cur * DIM + lane * 4];
        for (int q = 0; q < cnt; q++) {
            float4 xv_n = xv;
            float a_n = a_cur;
            if (q + 1 < cnt) {
                int s_n = __shfl_sync(0xffffffffu, __float_as_int(ed.x), q + 1);
                a_n = __shfl_sync(0xffffffffu, ed.y, q + 1);
                xv_n = *(const float4*)&x[(size_t)s_n * DIM + lane * 4];
            }
            float a = a_cur;
            float m0 = fmaxf(fmaf(a, w4.x, xv.x), 0.f) + 1e-7f;
            float m1 = fmaxf(fmaf(a, w4.y, xv.y), 0.f) + 1e-7f;
            float m2 = fmaxf(fmaf(a, w4.z, xv.z), 0.f) + 1e-7f;
            float m3 = fmaxf(fmaf(a, w4.w, xv.w), 0.f) + 1e-7f;
            float e0 = __expf(m0 * t), e1 = __expf(m1 * t);
            float e2 = __expf(m2 * t), e3 = __expf(m3 * t);
            aE.x += e0; aE.y += e1; aE.z += e2; aE.w += e3;
            aM.x = fmaf(m0, e0, aM.x); aM.y = fmaf(m1, e1, aM.y);
            aM.z = fmaf(m2, e2, aM.z); aM.w = fmaf(m3, e3, aM.w);
            xv = xv_n;
            a_cur = a_n;
        }
    }
    float4 xn = *(const float4*)&x[(size_t)gw * DIM + lane * 4];
    float4 h;
    h.x = aM.x / (aE.x + 1e-16f) + xn.x;
    h.y = aM.y / (aE.y + 1e-16f) + xn.y;
    h.z = aM.z / (aE.z + 1e-16f) + xn.z;
    h.w = aM.w / (aE.w + 1e-16f) + xn.w;
    *(float4*)&g_h[(size_t)gw * DIM + lane * 4] = h;
}

// ============================================================================
// tc256: g_h1[rows x 256] = g_h[rows x 128] @ W1[256 x 128]^T via mma.sync bf16 split
// ============================================================================
__global__ void __launch_bounds__(512, 1) tc256(
    const float* __restrict__ in, const u16* __restrict__ Bh, const u16* __restrict__ Bl,
    float* __restrict__ out)
{
    extern __shared__ __align__(16) char sm[];
    uint32_t sb = smem_u32(sm);
    int tid = threadIdx.x, wid = tid >> 5, lane = tid & 31;
    int row0 = blockIdx.x * 128;

    {
        const float4* bh = (const float4*)Bh;
        const float4* bl = (const float4*)Bl;
        float4* sh = (float4*)(sm + OFF_BH);
        float4* sl = (float4*)(sm + OFF_BH + 67584);
        for (int i = tid; i < 4224; i += 512) { sh[i] = bh[i]; sl[i] = bl[i]; }
    }
    for (int i = tid; i < 128 * 64; i += 512) {
        int r = i >> 6, k2 = (i & 63) << 1;
        int row = row0 + r;
        float2 hv = make_float2(0.f, 0.f);
        if (row < N_NODES) hv = *(const float2*)&in[(size_t)row * 128 + k2];
        uint32_t uh, ul;
        split2(hv.x, hv.y, uh, ul);
        *(uint32_t*)(sm + OFF_AH + r * ASTR + k2 * 2) = uh;
        *(uint32_t*)(sm + OFF_AL + r * ASTR + k2 * 2) = ul;
    }
    __syncthreads();

    int mrow0 = (wid & 7) * 16, nh = wid >> 3;
    uint32_t aRow = mrow0 + (lane & 7) + ((lane >> 3) & 1) * 8;
    uint32_t aAddrH = sb + OFF_AH + aRow * ASTR + (lane >> 4) * 16;
    uint32_t aAddrL = aAddrH + (OFF_AL - OFF_AH);
    uint32_t bLaneRow = (lane & 7) + ((lane >> 3) & 1) * 8;
    uint32_t bLaneN = ((lane >> 4) & 1) * 16 + nh * 256;

    float c[16][4];
#pragma unroll
    for (int t = 0; t < 16; t++)
#pragma unroll
        for (int q = 0; q < 4; q++) c[t][q] = 0.f;

#pragma unroll
    for (int kst = 0; kst < 8; kst++) {
        uint32_t ah[4], al[4];
        ldmx4(ah, aAddrH + kst * 32);
        ldmx4(al, aAddrL + kst * 32);
        uint32_t bAddr = sb + OFF_BH + (kst * 16 + bLaneRow) * 528 + bLaneN;
#pragma unroll
        for (int tp = 0; tp < 8; tp++) {
            uint32_t bh[4], bl[4];
            ldmx4t(bh, bAddr + tp * 32);
            ldmx4t(bl, bAddr + tp * 32 + 67584);
            mma16816(c[2 * tp],     ah, bh[0], bh[1]);
            mma16816(c[2 * tp],     al, bh[0], bh[1]);
            mma16816(c[2 * tp],     ah, bl[0], bl[1]);
            mma16816(c[2 * tp + 1], ah, bh[2], bh[3]);
            mma16816(c[2 * tp + 1], al, bh[2], bh[3]);
            mma16816(c[2 * tp + 1], ah, bl[2], bl[3]);
        }
    }

    int rbase = row0 + mrow0 + (lane >> 2);
    int cbase = nh * 128 + (lane & 3) * 2;
#pragma unroll
    for (int t = 0; t < 16; t++) {
        int n0 = cbase + t * 8;
        if (rbase < N_NODES)     *(float2*)&out[(size_t)rbase * 256 + n0]       = make_float2(c[t][0], c[t][1]);
        if (rbase + 8 < N_NODES) *(float2*)&out[(size_t)(rbase + 8) * 256 + n0] = make_float2(c[t][2], c[t][3]);
    }
}

// ---------------- bn column reduction over g_h1 ----------------
__global__ void __launch_bounds__(256) bn_reduce()
{
    int t = threadIdx.x;
    int r0 = blockIdx.x * 250, r1 = min(r0 + 250, N_NODES);
    float s = 0.f, q = 0.f;
    for (int row = r0; row < r1; row++) {
        float v = g_h1[(size_t)row * 256 + t];
        s += v; q += v * v;
    }
    atomicAdd(&g_bnsum[t], s);
    atomicAdd(&g_bnsum[256 + t], q);
}

__global__ void bn_stat(const float* __restrict__ bng, const float* __restrict__ bnb)
{
    int j = threadIdx.x;
    float s = g_bnsum[j], s2 = g_bnsum[256 + j];
    float mu = s * (1.0f / N_NODES);
    float var = s2 * (1.0f / N_NODES) - mu * mu;
    float rstd = rsqrtf(var + 1e-5f);
    float sc = rstd * bng[j];
    g_bnstat[j] = sc;
    g_bnstat[256 + j] = bnb[j] - mu * sc;
}

__device__ __forceinline__ float elu1(float v) { return v > 0.f ? v : expm1f(v); }

// ============================================================================
// tc_mlp2pq: out_x = ELU(LN(relu(bn(g_h1)) @ W2.T)); then PQ = out_x @ We' in-kernel
// ============================================================================
__global__ void __launch_bounds__(512, 1) tc_mlp2pq(
    const float* __restrict__ lng, const float* __restrict__ lnb, float* __restrict__ out_x)
{
    extern __shared__ __align__(16) char sm[];
    uint32_t sb = smem_u32(sm);
    int tid = threadIdx.x, wid = tid >> 5, lane = tid & 31;
    int row0 = blockIdx.x * 128;

    float* red  = (float*)sm;            // [128][4]
    float* lngs = (float*)(sm + 2048);
    float* lnbs = (float*)(sm + 2560);
    if (tid < 128) { lngs[tid] = lng[tid]; lnbs[tid] = lnb[tid]; }

    {
        const float4* bh = (const float4*)g_B2h;
        const float4* bl = (const float4*)g_B2l;
        float4* sh = (float4*)(sm + OFF_BH);
        float4* sl = (float4*)(sm + OFF_BH + 69632);
        for (int i = tid; i < 4352; i += 512) { sh[i] = bh[i]; sl[i] = bl[i]; }
    }

    int mrow0 = (wid & 7) * 16, nh = wid >> 3;
    uint32_t aRow = mrow0 + (lane & 7) + ((lane >> 3) & 1) * 8;
    uint32_t aAddrH = sb + OFF_AH + aRow * ASTR + (lane >> 4) * 16;
    uint32_t aAddrL = aAddrH + (OFF_AL - OFF_AH);
    uint32_t bLaneRow = (lane & 7) + ((lane >> 3) & 1) * 8;
    uint32_t bLaneN = ((lane >> 4) & 1) * 16 + nh * 128;

    float c[8][4];
#pragma unroll
    for (int t = 0; t < 8; t++)
#pragma unroll
        for (int q = 0; q < 4; q++) c[t][q] = 0.f;

#pragma unroll
    for (int s = 0; s < 2; s++) {
        __syncthreads();
        for (int i = tid; i < 128 * 64; i += 512) {
            int r = i >> 6, k2 = (i & 63) << 1;
            int row = row0 + r;
            float v0 = 0.f, v1 = 0.f;
            if (row < N_NODES) {
                int kc = s * 128 + k2;
                float2 hv = *(const float2*)&g_h1[(size_t)row * 256 + kc];
                v0 = fmaxf(fmaf(hv.x, g_bnstat[kc],     g_bnstat[256 + kc]),     0.f);
                v1 = fmaxf(fmaf(hv.y, g_bnstat[kc + 1], g_bnstat[256 + kc + 1]), 0.f);
            }
            uint32_t uh, ul;
            split2(v0, v1, uh, ul);
            *(uint32_t*)(sm + OFF_AH + r * ASTR + k2 * 2) = uh;
            *(uint32_t*)(sm + OFF_AL + r * ASTR + k2 * 2) = ul;
        }
        __syncthreads();

#pragma unroll
        for (int kst = 0; kst < 8; kst++) {
            uint32_t ah[4], al[4];
            ldmx4(ah, aAddrH + kst * 32);
            ldmx4(al, aAddrL + kst * 32);
            uint32_t bAddr = sb + OFF_BH + (s * 128 + kst * 16 + bLaneRow) * 272 + bLaneN;
#pragma unroll
            for (int tp = 0; tp < 4; tp++) {
                uint32_t bh[4], bl[4];
                ldmx4t(bh, bAddr + tp * 32);
                ldmx4t(bl, bAddr + tp * 32 + 69632);
                mma16816(c[2 * tp],     ah, bh[0], bh[1]);
                mma16816(c[2 * tp],     al, bh[0], bh[1]);
                mma16816(c[2 * tp],     ah, bl[0], bl[1]);
                mma16816(c[2 * tp + 1], ah, bh[2], bh[3]);
                mma16816(c[2 * tp + 1], al, bh[2], bh[3]);
                mma16816(c[2 * tp + 1], ah, bl[2], bl[3]);
            }
        }
    }

    // ---- barrier: everyone done reading B2, start loading B3 over it ----
    __syncthreads();
    {
        const float4* bh = (const float4*)g_B3h;
        const float4* bl = (const float4*)g_B3l;
        float4* sh = (float4*)(sm + OFF_BH);
        float4* sl = (float4*)(sm + OFF_BH + 67584);
        for (int i = tid; i < 4224; i += 512) { sh[i] = bh[i]; sl[i] = bl[i]; }
    }

    // ---- LN + ELU epilogue; write out_x AND bf16-split into A smem ----
    float s1a = 0.f, s2a = 0.f, s1b = 0.f, s2b = 0.f;
#pragma unroll
    for (int t = 0; t < 8; t++) {
        s1a += c[t][0] + c[t][1];
        s2a += c[t][0] * c[t][0] + c[t][1] * c[t][1];
        s1b += c[t][2] + c[t][3];
        s2b += c[t][2] * c[t][2] + c[t][3] * c[t][3];
    }
#pragma unroll
    for (int o = 1; o < 4; o <<= 1) {
        s1a += __shfl_xor_sync(~0u, s1a, o);
        s2a += __shfl_xor_sync(~0u, s2a, o);
        s1b += __shfl_xor_sync(~0u, s1b, o);
        s2b += __shfl_xor_sync(~0u, s2b, o);
    }
    __syncthreads();
    if ((lane & 3) == 0) {
        int r = mrow0 + (lane >> 2);
        red[r * 4 + nh * 2]           = s1a;
        red[r * 4 + nh * 2 + 1]       = s2a;
        red[(r + 8) * 4 + nh * 2]     = s1b;
        red[(r + 8) * 4 + nh * 2 + 1] = s2b;
    }
    __syncthreads();
    {
        int ra = mrow0 + (lane >> 2), rb = ra + 8;
        float mua = (red[ra * 4] + red[ra * 4 + 2]) * (1.f / 128.f);
        float vara = (red[ra * 4 + 1] + red[ra * 4 + 3]) * (1.f / 128.f) - mua * mua;
        float rsa = rsqrtf(vara + 1e-5f);
        float mub = (red[rb * 4] + red[rb * 4 + 2]) * (1.f / 128.f);
        float varb = (red[rb * 4 + 1] + red[rb * 4 + 3]) * (1.f / 128.f) - mub * mub;
        float rsb = rsqrtf(varb + 1e-5f);
        int rowa = row0 + ra, rowb = row0 + rb;
#pragma unroll
        for (int t = 0; t < 8; t++) {
            int col = nh * 64 + t * 8 + (lane & 3) * 2;
            float oax = elu1((c[t][0] - mua) * rsa * lngs[col]     + lnbs[col]);
            float oay = elu1((c[t][1] - mua) * rsa * lngs[col + 1] + lnbs[col + 1]);
            float obx = elu1((c[t][2] - mub) * rsb * lngs[col]     + lnbs[col]);
            float oby = elu1((c[t][3] - mub) * rsb * lngs[col + 1] + lnbs[col + 1]);
            if (rowa < N_NODES) *(float2*)&out_x[(size_t)rowa * DIM + col] = make_float2(oax, oay);
            if (rowb < N_NODES) *(float2*)&out_x[(size_t)rowb * DIM + col] = make_float2(obx, oby);
            uint32_t uh, ul;
            split2(oax, oay, uh, ul);
            *(uint32_t*)(sm + OFF_AH + ra * ASTR + col * 2) = uh;
            *(uint32_t*)(sm + OFF_AL + ra * ASTR + col * 2) = ul;
            split2(obx, oby, uh, ul);
            *(uint32_t*)(sm + OFF_AH + rb * ASTR + col * 2) = uh;
            *(uint32_t*)(sm + OFF_AL + rb * ASTR + col * 2) = ul;
        }
    }
    __syncthreads();

    // ---- second MMA: PQ = out_x @ [WeL|WeR]^T (out 256 cols) ----
    uint32_t bLaneN2 = ((lane >> 4) & 1) * 16 + nh * 256;
    float c2[16][4];
#pragma unroll
    for (int t = 0; t < 16; t++)
#pragma unroll
        for (int q = 0; q < 4; q++) c2[t][q] = 0.f;

#pragma unroll
    for (int kst = 0; kst < 8; kst++) {
        uint32_t ah[4], al[4];
        ldmx4(ah, aAddrH + kst * 32);
        ldmx4(al, aAddrL + kst * 32);
        uint32_t bAddr = sb + OFF_BH + (kst * 16 + bLaneRow) * 528 + bLaneN2;
#pragma unroll
        for (int tp = 0; tp < 8; tp++) {
            uint32_t bh[4], bl[4];
            ldmx4t(bh, bAddr + tp * 32);
            ldmx4t(bl, bAddr + tp * 32 + 67584);
            mma16816(c2[2 * tp],     ah, bh[0], bh[1]);
            mma16816(c2[2 * tp],     al, bh[0], bh[1]);
            mma16816(c2[2 * tp],     ah, bl[0], bl[1]);
            mma16816(c2[2 * tp + 1], ah, bh[2], bh[3]);
            mma16816(c2[2 * tp + 1], al, bh[2], bh[3]);
            mma16816(c2[2 * tp + 1], ah, bl[2], bl[3]);
        }
    }

    int rbase = row0 + mrow0 + (lane >> 2);
    int cbase = nh * 128 + (lane & 3) * 2;
#pragma unroll
    for (int t = 0; t < 16; t++) {
        int n0 = cbase + t * 8;
        if (rbase < N_NODES)     *(float2*)&g_PQ[(size_t)rbase * 256 + n0]       = make_float2(c2[t][0], c2[t][1]);
        if (rbase + 8 < N_NODES) *(float2*)&g_PQ[(size_t)(rbase + 8) * 256 + n0] = make_float2(c2[t][2], c2[t][3]);
    }
}

// ---------------- edge_out: warp per node; prefetched P gather ----------------
__global__ void __launch_bounds__(256) edge_out(
    const float* __restrict__ be, const float* __restrict__ lng, const float* __restrict__ lnb,
    float* __restrict__ out_e)
{
    int gw = (blockIdx.x * 256 + threadIdx.x) >> 5;   // node
    int lane = threadIdx.x & 31;
    if (gw >= N_NODES) return;
    int j0 = lane * 4;
    float4 gv = *(const float4*)(lng + j0);
    float4 bv = *(const float4*)(lnb + j0);
    float4 qb;
    {
        float4 bev = *(const float4*)(be + j0);
        float4 qv = *(const float4*)&g_PQ[(size_t)gw * 256 + 128 + j0];
        qb.x = qv.x + bev.x; qb.y = qv.y + bev.y;
        qb.z = qv.z + bev.z; qb.w = qv.w + bev.w;
    }
    int beg = g_off[gw];
    int end = (gw == N_NODES - 1) ? N_EDGES : g_off[gw + 1];

    for (int b = beg; b < end; b += 32) {
        int j = b + lane;
        int sl = 0, el = 0;
        if (j < end) { float4 e4 = g_edge[j]; sl = __float_as_int(e4.x); el = __float_as_int(e4.z); }
        int cnt = min(32, end - b);
        int s_cur = __shfl_sync(0xffffffffu, sl, 0);
        int e_cur = __shfl_sync(0xffffffffu, el, 0);
        float4 p = *(const float4*)&g_PQ[(size_t)s_cur * 256 + j0];
        for (int q = 0; q < cnt; q++) {
            float4 p_n = p;
            int e_n = e_cur;
            if (q + 1 < cnt) {
                int s_n = __shfl_sync(0xffffffffu, sl, q + 1);
                e_n = __shfl_sync(0xffffffffu, el, q + 1);
                p_n = *(const float4*)&g_PQ[(size_t)s_n * 256 + j0];
            }
            float v0 = p.x + qb.x, v1 = p.y + qb.y, v2 = p.z + qb.z, v3 = p.w + qb.w;
            float g0 = 0.5f * v0 * (1.f + erff(v0 * 0.70710678118654752f));
            float g1 = 0.5f * v1 * (1.f + erff(v1 * 0.70710678118654752f));
            float g2 = 0.5f * v2 * (1.f + erff(v2 * 0.70710678118654752f));
            float g3 = 0.5f * v3 * (1.f + erff(v3 * 0.70710678118654752f));
            float s1 = g0 + g1 + g2 + g3;
            float s2 = g0 * g0 + g1 * g1 + g2 * g2 + g3 * g3;
#pragma unroll
            for (int o = 16; o > 0; o >>= 1) {
                s1 += __shfl_xor_sync(0xffffffffu, s1, o);
                s2 += __shfl_xor_sync(0xffffffffu, s2, o);
            }
            float mu = s1 * (1.f / 128.f);
            float var = s2 * (1.f / 128.f) - mu * mu;
            float rstd = rsqrtf(var + 1e-5f);
            float4 o;
            o.x = (g0 - mu) * rstd * gv.x + bv.x;
            o.y = (g1 - mu) * rstd * gv.y + bv.y;
            o.z = (g2 - mu) * rstd * gv.z + bv.z;
            o.w = (g3 - mu) * rstd * gv.w + bv.w;
            *(float4*)(out_e + (size_t)e_cur * DIM + j0) = o;
            p = p_n;
            e_cur = e_n;
        }
    }
}

// ---------------- launch ----------------
extern "C" void kernel_launch(void* const* d_in, const int* in_sizes, int n_in,
                              void* d_out, int out_size)
{
    const float* x      = (const float*)d_in[0];
    const int*   ei     = (const int*)  d_in[1];
    const float* ea     = (const float*)d_in[2];
    const float* W_edge = (const float*)d_in[3];
    const float* tptr   = (const float*)d_in[4];
    const float* W1     = (const float*)d_in[5];
    const float* bng    = (const float*)d_in[6];
    const float* bnb    = (const float*)d_in[7];
    const float* W2     = (const float*)d_in[8];
    const float* lng    = (const float*)d_in[9];
    const float* lnb    = (const float*)d_in[10];
    const float* We     = (const float*)d_in[11];
    const float* be     = (const float*)d_in[12];
    const float* lneg   = (const float*)d_in[13];
    const float* lneb   = (const float*)d_in[14];

    const int* src = ei;
    const int* dst = ei + N_EDGES;

    float* out_x = (float*)d_out;
    float* out_e = out_x + (size_t)N_NODES * DIM;

    void *bnp, *b1h, *b1l, *ghp, *h1p;
    cudaGetSymbolAddress(&bnp, g_bnsum);
    cudaGetSymbolAddress(&b1h, g_B1h);
    cudaGetSymbolAddress(&b1l, g_B1l);
    cudaGetSymbolAddress(&ghp, g_h);
    cudaGetSymbolAddress(&h1p, g_h1);

    cudaFuncSetAttribute(tc256, cudaFuncAttributeMaxDynamicSharedMemorySize, SM_TC256);
    cudaFuncSetAttribute(tc_mlp2pq, cudaFuncAttributeMaxDynamicSharedMemorySize, SM_MLP2);

    int eblocks256 = (N_EDGES + 255) / 256;
    int ablocks = (N_NODES * 32 + 255) / 256;
    int tblocks = (N_NODES + 127) / 128;

    prep_all<<<384 + 196, 256>>>(W1, We, W2);                    // also zeros g_cnt
    hist<<<eblocks256, 256>>>(dst);
    scan50k<<<1, 1024>>>();
    scatter<<<eblocks256, 256>>>(src, dst, ea);
    aggregate<<<ablocks, 256>>>(x, W_edge, tptr);                // expected profiled slot
    cudaMemsetAsync(bnp, 0, sizeof(float) * 512, 0);

    tc256<<<tblocks, 512, SM_TC256>>>((const float*)ghp, (const u16*)b1h, (const u16*)b1l, (float*)h1p);
    bn_reduce<<<200, 256>>>();
    bn_stat<<<1, 256>>>(bng, bnb);
    tc_mlp2pq<<<tblocks, 512, SM_MLP2>>>(lng, lnb, out_x);
    edge_out<<<ablocks, 256>>>(be, lneg, lneb, out_e);
}

// round 12
// speedup vs baseline: 1.2045x; 1.0197x over previous
#include <cuda_runtime.h>
#include <cuda_bf16.h>
#include <math.h>
#include <stdint.h>

#define N_NODES 50000
#define N_EDGES 800000
#define DIM 128

typedef unsigned long long ull;
typedef unsigned short u16;

// ---------------- scratch ----------------
__device__ float g_h[(size_t)N_NODES * DIM];         // aggr + x  (gemm1 input)
__device__ float g_h1[(size_t)N_NODES * 256];        // h @ W1.T
__device__ float g_PQ[(size_t)N_NODES * 256];        // [P | Q] per node
__device__ float4 g_edge[(size_t)N_EDGES];           // sorted (src_asf, ea, eid_asf, 0)
__device__ int g_cnt[N_NODES];
__device__ int g_off[N_NODES];
__device__ int g_cur[N_NODES];
__device__ float g_bnsum[512];
__device__ float g_bnstat[512];
// pre-split bf16 weights, [k][n] layout, padded rows
__device__ __align__(16) u16 g_B1h[128 * 264], g_B1l[128 * 264];   // W1:  k<128, n<256, stride 264
__device__ __align__(16) u16 g_B3h[128 * 264], g_B3l[128 * 264];   // We-remap: k<128, n<256
__device__ __align__(16) u16 g_B2h[256 * 136], g_B2l[256 * 136];   // W2:  k<256, n<128, stride 136

// ---------------- mma helpers ----------------
__device__ __forceinline__ uint32_t smem_u32(const void* p) {
    uint32_t a;
    asm("{ .reg .u64 t; cvta.to.shared.u64 t, %1; cvt.u32.u64 %0, t; }" : "=r"(a) : "l"(p));
    return a;
}
__device__ __forceinline__ void ldmx4(uint32_t* r, uint32_t addr) {
    asm volatile("ldmatrix.sync.aligned.m8n8.x4.shared.b16 {%0,%1,%2,%3}, [%4];"
        : "=r"(r[0]), "=r"(r[1]), "=r"(r[2]), "=r"(r[3]) : "r"(addr));
}
__device__ __forceinline__ void ldmx4t(uint32_t* r, uint32_t addr) {
    asm volatile("ldmatrix.sync.aligned.m8n8.x4.trans.shared.b16 {%0,%1,%2,%3}, [%4];"
        : "=r"(r[0]), "=r"(r[1]), "=r"(r[2]), "=r"(r[3]) : "r"(addr));
}
__device__ __forceinline__ void mma16816(float* c, const uint32_t* a, uint32_t b0, uint32_t b1) {
    asm volatile("mma.sync.aligned.m16n8k16.row.col.f32.bf16.bf16.f32 "
        "{%0,%1,%2,%3}, {%4,%5,%6,%7}, {%8,%9}, {%0,%1,%2,%3};"
        : "+f"(c[0]), "+f"(c[1]), "+f"(c[2]), "+f"(c[3])
        : "r"(a[0]), "r"(a[1]), "r"(a[2]), "r"(a[3]), "r"(b0), "r"(b1));
}
__device__ __forceinline__ void split2(float a, float b, uint32_t& uh, uint32_t& ul) {
    __nv_bfloat16 h0 = __float2bfloat16_rn(a), h1 = __float2bfloat16_rn(b);
    float r0 = a - __bfloat162float(h0), r1 = b - __bfloat162float(h1);
    __nv_bfloat16 l0 = __float2bfloat16_rn(r0), l1 = __float2bfloat16_rn(r1);
    uh = (uint32_t)(*(u16*)&h0) | ((uint32_t)(*(u16*)&h1) << 16);
    ul = (uint32_t)(*(u16*)&l0) | ((uint32_t)(*(u16*)&l1) << 16);
}

// fast exact GELU: erf via Abramowitz-Stegun 7.1.26 (|abs err| <= 1.5e-7)
__device__ __forceinline__ float fgelu(float v) {
    float x = fabsf(v) * 0.70710678118654752f;
    float t = __fdividef(1.0f, fmaf(0.3275911f, x, 1.0f));
    float poly = t * fmaf(t, fmaf(t, fmaf(t, fmaf(t, 1.061405429f, -1.453152027f),
                  1.421413741f), -0.284496736f), 0.254829592f);
    float ex = __expf(-x * x);
    float erf_abs = fmaf(-poly, ex, 1.0f);
    float erf_v = copysignf(erf_abs, v);
    return 0.5f * v * (1.0f + erf_v);
}

// SMEM layout (bytes)
#define CTRL 4096
#define ASTR 272                       // A row stride: 128 bf16 + 8 pad
#define OFF_AH CTRL
#define OFF_AL (OFF_AH + 128 * ASTR)
#define OFF_BH (OFF_AL + 128 * ASTR)   // 73728
#define SM_TC256 (OFF_BH + 2 * 67584)
#define SM_MLP2  (OFF_BH + 2 * 69632)  // 212992 (also holds B3 later: 2*67584)

// ---------------- weight prep + cnt zeroing (single kernel) ----------------
__global__ void __launch_bounds__(256) prep_all(
    const float* __restrict__ W1, const float* __restrict__ We, const float* __restrict__ W2)
{
    int b = blockIdx.x;
    if (b >= 384) {      // zero g_cnt
        int i = (b - 384) * 256 + threadIdx.x;
        if (i < N_NODES) g_cnt[i] = 0;
        return;
    }
    int li = (b % 128) * 256 + threadIdx.x;
    if (b < 256) {   // W1 (b<128) or We (128<=b<256): out [k<128][n<256] stride 264
        int j = li >> 7, k = li & 127;
        float v = (b < 128) ? W1[j * 128 + k]
                : ((j < 128) ? We[j * 256 + k] : We[(j - 128) * 256 + 128 + k]);
        __nv_bfloat16 hb = __float2bfloat16_rn(v);
        float rr = v - __bfloat162float(hb);
        __nv_bfloat16 lb = __float2bfloat16_rn(rr);
        u16* Bh = (b < 128) ? g_B1h : g_B3h;
        u16* Bl = (b < 128) ? g_B1l : g_B3l;
        Bh[k * 264 + j] = *(u16*)&hb;
        Bl[k * 264 + j] = *(u16*)&lb;
    } else {         // W2: out [k<256][n<128] stride 136
        int j = li >> 8, k = li & 255;
        float v = W2[j * 256 + k];
        __nv_bfloat16 hb = __float2bfloat16_rn(v);
        float rr = v - __bfloat162float(hb);
        __nv_bfloat16 lb = __float2bfloat16_rn(rr);
        g_B2h[k * 136 + j] = *(u16*)&hb;
        g_B2l[k * 136 + j] = *(u16*)&lb;
    }
}

// ---------------- edge sort: hist / scan / scatter ----------------
__global__ void __launch_bounds__(256) hist(const int* __restrict__ dst)
{
    int e = blockIdx.x * 256 + threadIdx.x;
    if (e < N_EDGES) atomicAdd(&g_cnt[dst[e]], 1);
}

__global__ void __launch_bounds__(1024) scan50k()
{
    __shared__ int wsum[32];
    __shared__ int sh_carry;
    int tid = threadIdx.x, lane = tid & 31, w = tid >> 5;
    if (tid == 0) sh_carry = 0;
    __syncthreads();
    for (int base = 0; base < N_NODES; base += 1024) {
        int i = base + tid;
        int v = (i < N_NODES) ? g_cnt[i] : 0;
        int x = v;
#pragma unroll
        for (int o = 1; o < 32; o <<= 1) { int y = __shfl_up_sync(~0u, x, o); if (lane >= o) x += y; }
        if (lane == 31) wsum[w] = x;
        __syncthreads();
        if (w == 0) {
            int s = wsum[lane];
#pragma unroll
            for (int o = 1; o < 32; o <<= 1) { int y = __shfl_up_sync(~0u, s, o); if (lane >= o) s += y; }
            wsum[lane] = s;
        }
        __syncthreads();
        int warp_excl = (w == 0) ? 0 : wsum[w - 1];
        int carry = sh_carry;
        int excl = carry + warp_excl + x - v;
        if (i < N_NODES) { g_off[i] = excl; g_cur[i] = excl; }
        __syncthreads();
        if (tid == 1023) sh_carry = carry + wsum[31];
        __syncthreads();
    }
}

__global__ void __launch_bounds__(256) scatter(
    const int* __restrict__ src, const int* __restrict__ dst, const float* __restrict__ ea)
{
    int e = blockIdx.x * 256 + threadIdx.x;
    if (e >= N_EDGES) return;
    int d = dst[e];
    int pos = atomicAdd(&g_cur[d], 1);
    g_edge[pos] = make_float4(__int_as_float(src[e]), ea[e], __int_as_float(e), 0.f);
}

// ---------------- aggregate: warp per node, prefetched gather ----------------
__global__ void __launch_bounds__(256) aggregate(
    const float* __restrict__ x, const float* __restrict__ W_edge, const float* __restrict__ tptr)
{
    int gw = (blockIdx.x * 256 + threadIdx.x) >> 5;
    int lane = threadIdx.x & 31;
    if (gw >= N_NODES) return;
    const float t = tptr[0];
    float4 w4 = *(const float4*)&W_edge[lane * 4];

    int beg = g_off[gw];
    int end = (gw == N_NODES - 1) ? N_EDGES : g_off[gw + 1];

    float4 aE = make_float4(0.f, 0.f, 0.f, 0.f);
    float4 aM = make_float4(0.f, 0.f, 0.f, 0.f);

    for (int b = beg; b < end; b += 32) {
        int j = b + lane;
        float2 ed = make_float2(0.f, 0.f);
        if (j < end) { float4 e4 = g_edge[j]; ed = make_float2(e4.x, e4.y); }
        int cnt = min(32, end - b);
        int s_cur = __shfl_sync(0xffffffffu, __float_as_int(ed.x), 0);
        float a_cur = __shfl_sync(0xffffffffu, ed.y, 0);
        float4 xv = *(const float4*)&x[(size_t)s_cur * DIM + lane * 4];
        for (int q = 0; q < cnt; q++) {
            float4 xv_n = xv;
            float a_n = a_cur;
            if (q + 1 < cnt) {
                int s_n = __shfl_sync(0xffffffffu, __float_as_int(ed.x), q + 1);
                a_n = __shfl_sync(0xffffffffu, ed.y, q + 1);
                xv_n = *(const float4*)&x[(size_t)s_n * DIM + lane * 4];
            }
            float a = a_cur;
            float m0 = fmaxf(fmaf(a, w4.x, xv.x), 0.f) + 1e-7f;
            float m1 = fmaxf(fmaf(a, w4.y, xv.y), 0.f) + 1e-7f;
            float m2 = fmaxf(fmaf(a, w4.z, xv.z), 0.f) + 1e-7f;
            float m3 = fmaxf(fmaf(a, w4.w, xv.w), 0.f) + 1e-7f;
            float e0 = __expf(m0 * t), e1 = __expf(m1 * t);
            float e2 = __expf(m2 * t), e3 = __expf(m3 * t);
            aE.x += e0; aE.y += e1; aE.z += e2; aE.w += e3;
            aM.x = fmaf(m0, e0, aM.x); aM.y = fmaf(m1, e1, aM.y);
            aM.z = fmaf(m2, e2, aM.z); aM.w = fmaf(m3, e3, aM.w);
            xv = xv_n;
            a_cur = a_n;
        }
    }
    float4 xn = *(const float4*)&x[(size_t)gw * DIM + lane * 4];
    float4 h;
    h.x = aM.x / (aE.x + 1e-16f) + xn.x;
    h.y = aM.y / (aE.y + 1e-16f) + xn.y;
    h.z = aM.z / (aE.z + 1e-16f) + xn.z;
    h.w = aM.w / (aE.w + 1e-16f) + xn.w;
    *(float4*)&g_h[(size_t)gw * DIM + lane * 4] = h;
}

// ============================================================================
// tc256: g_h1[rows x 256] = g_h[rows x 128] @ W1[256 x 128]^T via mma.sync bf16 split
// ============================================================================
__global__ void __launch_bounds__(512, 1) tc256(
    const float* __restrict__ in, const u16* __restrict__ Bh, const u16* __restrict__ Bl,
    float* __restrict__ out)
{
    extern __shared__ __align__(16) char sm[];
    uint32_t sb = smem_u32(sm);
    int tid = threadIdx.x, wid = tid >> 5, lane = tid & 31;
    int row0 = blockIdx.x * 128;

    {
        const float4* bh = (const float4*)Bh;
        const float4* bl = (const float4*)Bl;
        float4* sh = (float4*)(sm + OFF_BH);
        float4* sl = (float4*)(sm + OFF_BH + 67584);
        for (int i = tid; i < 4224; i += 512) { sh[i] = bh[i]; sl[i] = bl[i]; }
    }
    for (int i = tid; i < 128 * 64; i += 512) {
        int r = i >> 6, k2 = (i & 63) << 1;
        int row = row0 + r;
        float2 hv = make_float2(0.f, 0.f);
        if (row < N_NODES) hv = *(const float2*)&in[(size_t)row * 128 + k2];
        uint32_t uh, ul;
        split2(hv.x, hv.y, uh, ul);
        *(uint32_t*)(sm + OFF_AH + r * ASTR + k2 * 2) = uh;
        *(uint32_t*)(sm + OFF_AL + r * ASTR + k2 * 2) = ul;
    }
    __syncthreads();

    int mrow0 = (wid & 7) * 16, nh = wid >> 3;
    uint32_t aRow = mrow0 + (lane & 7) + ((lane >> 3) & 1) * 8;
    uint32_t aAddrH = sb + OFF_AH + aRow * ASTR + (lane >> 4) * 16;
    uint32_t aAddrL = aAddrH + (OFF_AL - OFF_AH);
    uint32_t bLaneRow = (lane & 7) + ((lane >> 3) & 1) * 8;
    uint32_t bLaneN = ((lane >> 4) & 1) * 16 + nh * 256;

    float c[16][4];
#pragma unroll
    for (int t = 0; t < 16; t++)
#pragma unroll
        for (int q = 0; q < 4; q++) c[t][q] = 0.f;

#pragma unroll
    for (int kst = 0; kst < 8; kst++) {
        uint32_t ah[4], al[4];
        ldmx4(ah, aAddrH + kst * 32);
        ldmx4(al, aAddrL + kst * 32);
        uint32_t bAddr = sb + OFF_BH + (kst * 16 + bLaneRow) * 528 + bLaneN;
#pragma unroll
        for (int tp = 0; tp < 8; tp++) {
            uint32_t bh[4], bl[4];
            ldmx4t(bh, bAddr + tp * 32);
            ldmx4t(bl, bAddr + tp * 32 + 67584);
            mma16816(c[2 * tp],     ah, bh[0], bh[1]);
            mma16816(c[2 * tp],     al, bh[0], bh[1]);
            mma16816(c[2 * tp],     ah, bl[0], bl[1]);
            mma16816(c[2 * tp + 1], ah, bh[2], bh[3]);
            mma16816(c[2 * tp + 1], al, bh[2], bh[3]);
            mma16816(c[2 * tp + 1], ah, bl[2], bl[3]);
        }
    }

    int rbase = row0 + mrow0 + (lane >> 2);
    int cbase = nh * 128 + (lane & 3) * 2;
#pragma unroll
    for (int t = 0; t < 16; t++) {
        int n0 = cbase + t * 8;
        if (rbase < N_NODES)     *(float2*)&out[(size_t)rbase * 256 + n0]       = make_float2(c[t][0], c[t][1]);
        if (rbase + 8 < N_NODES) *(float2*)&out[(size_t)(rbase + 8) * 256 + n0] = make_float2(c[t][2], c[t][3]);
    }
}

// ---------------- bn column reduction over g_h1 ----------------
__global__ void __launch_bounds__(256) bn_reduce()
{
    int t = threadIdx.x;
    int r0 = blockIdx.x * 250, r1 = min(r0 + 250, N_NODES);
    float s = 0.f, q = 0.f;
    for (int row = r0; row < r1; row++) {
        float v = g_h1[(size_t)row * 256 + t];
        s += v; q += v * v;
    }
    atomicAdd(&g_bnsum[t], s);
    atomicAdd(&g_bnsum[256 + t], q);
}

__global__ void bn_stat(const float* __restrict__ bng, const float* __restrict__ bnb)
{
    int j = threadIdx.x;
    float s = g_bnsum[j], s2 = g_bnsum[256 + j];
    float mu = s * (1.0f / N_NODES);
    float var = s2 * (1.0f / N_NODES) - mu * mu;
    float rstd = rsqrtf(var + 1e-5f);
    float sc = rstd * bng[j];
    g_bnstat[j] = sc;
    g_bnstat[256 + j] = bnb[j] - mu * sc;
}

__device__ __forceinline__ float elu1(float v) { return v > 0.f ? v : expm1f(v); }

// ============================================================================
// tc_mlp2pq: out_x = ELU(LN(relu(bn(g_h1)) @ W2.T)); then PQ = out_x @ We' in-kernel
// ============================================================================
__global__ void __launch_bounds__(512, 1) tc_mlp2pq(
    const float* __restrict__ lng, const float* __restrict__ lnb, float* __restrict__ out_x)
{
    extern __shared__ __align__(16) char sm[];
    uint32_t sb = smem_u32(sm);
    int tid = threadIdx.x, wid = tid >> 5, lane = tid & 31;
    int row0 = blockIdx.x * 128;

    float* red  = (float*)sm;            // [128][4]
    float* lngs = (float*)(sm + 2048);
    float* lnbs = (float*)(sm + 2560);
    if (tid < 128) { lngs[tid] = lng[tid]; lnbs[tid] = lnb[tid]; }

    {
        const float4* bh = (const float4*)g_B2h;
        const float4* bl = (const float4*)g_B2l;
        float4* sh = (float4*)(sm + OFF_BH);
        float4* sl = (float4*)(sm + OFF_BH + 69632);
        for (int i = tid; i < 4352; i += 512) { sh[i] = bh[i]; sl[i] = bl[i]; }
    }

    int mrow0 = (wid & 7) * 16, nh = wid >> 3;
    uint32_t aRow = mrow0 + (lane & 7) + ((lane >> 3) & 1) * 8;
    uint32_t aAddrH = sb + OFF_AH + aRow * ASTR + (lane >> 4) * 16;
    uint32_t aAddrL = aAddrH + (OFF_AL - OFF_AH);
    uint32_t bLaneRow = (lane & 7) + ((lane >> 3) & 1) * 8;
    uint32_t bLaneN = ((lane >> 4) & 1) * 16 + nh * 128;

    float c[8][4];
#pragma unroll
    for (int t = 0; t < 8; t++)
#pragma unroll
        for (int q = 0; q < 4; q++) c[t][q] = 0.f;

#pragma unroll
    for (int s = 0; s < 2; s++) {
        __syncthreads();
        for (int i = tid; i < 128 * 64; i += 512) {
            int r = i >> 6, k2 = (i & 63) << 1;
            int row = row0 + r;
            float v0 = 0.f, v1 = 0.f;
            if (row < N_NODES) {
                int kc = s * 128 + k2;
                float2 hv = *(const float2*)&g_h1[(size_t)row * 256 + kc];
                v0 = fmaxf(fmaf(hv.x, g_bnstat[kc],     g_bnstat[256 + kc]),     0.f);
                v1 = fmaxf(fmaf(hv.y, g_bnstat[kc + 1], g_bnstat[256 + kc + 1]), 0.f);
            }
            uint32_t uh, ul;
            split2(v0, v1, uh, ul);
            *(uint32_t*)(sm + OFF_AH + r * ASTR + k2 * 2) = uh;
            *(uint32_t*)(sm + OFF_AL + r * ASTR + k2 * 2) = ul;
        }
        __syncthreads();

#pragma unroll
        for (int kst = 0; kst < 8; kst++) {
            uint32_t ah[4], al[4];
            ldmx4(ah, aAddrH + kst * 32);
            ldmx4(al, aAddrL + kst * 32);
            uint32_t bAddr = sb + OFF_BH + (s * 128 + kst * 16 + bLaneRow) * 272 + bLaneN;
#pragma unroll
            for (int tp = 0; tp < 4; tp++) {
                uint32_t bh[4], bl[4];
                ldmx4t(bh, bAddr + tp * 32);
                ldmx4t(bl, bAddr + tp * 32 + 69632);
                mma16816(c[2 * tp],     ah, bh[0], bh[1]);
                mma16816(c[2 * tp],     al, bh[0], bh[1]);
                mma16816(c[2 * tp],     ah, bl[0], bl[1]);
                mma16816(c[2 * tp + 1], ah, bh[2], bh[3]);
                mma16816(c[2 * tp + 1], al, bh[2], bh[3]);
                mma16816(c[2 * tp + 1], ah, bl[2], bl[3]);
            }
        }
    }

    // ---- barrier: everyone done reading B2, start loading B3 over it ----
    __syncthreads();
    {
        const float4* bh = (const float4*)g_B3h;
        const float4* bl = (const float4*)g_B3l;
        float4* sh = (float4*)(sm + OFF_BH);
        float4* sl = (float4*)(sm + OFF_BH + 67584);
        for (int i = tid; i < 4224; i += 512) { sh[i] = bh[i]; sl[i] = bl[i]; }
    }

    // ---- LN + ELU epilogue; write out_x AND bf16-split into A smem ----
    float s1a = 0.f, s2a = 0.f, s1b = 0.f, s2b = 0.f;
#pragma unroll
    for (int t = 0; t < 8; t++) {
        s1a += c[t][0] + c[t][1];
        s2a += c[t][0] * c[t][0] + c[t][1] * c[t][1];
        s1b += c[t][2] + c[t][3];
        s2b += c[t][2] * c[t][2] + c[t][3] * c[t][3];
    }
#pragma unroll
    for (int o = 1; o < 4; o <<= 1) {
        s1a += __shfl_xor_sync(~0u, s1a, o);
        s2a += __shfl_xor_sync(~0u, s2a, o);
        s1b += __shfl_xor_sync(~0u, s1b, o);
        s2b += __shfl_xor_sync(~0u, s2b, o);
    }
    __syncthreads();
    if ((lane & 3) == 0) {
        int r = mrow0 + (lane >> 2);
        red[r * 4 + nh * 2]           = s1a;
        red[r * 4 + nh * 2 + 1]       = s2a;
        red[(r + 8) * 4 + nh * 2]     = s1b;
        red[(r + 8) * 4 + nh * 2 + 1] = s2b;
    }
    __syncthreads();
    {
        int ra = mrow0 + (lane >> 2), rb = ra + 8;
        float mua = (red[ra * 4] + red[ra * 4 + 2]) * (1.f / 128.f);
        float vara = (red[ra * 4 + 1] + red[ra * 4 + 3]) * (1.f / 128.f) - mua * mua;
        float rsa = rsqrtf(vara + 1e-5f);
        float mub = (red[rb * 4] + red[rb * 4 + 2]) * (1.f / 128.f);
        float varb = (red[rb * 4 + 1] + red[rb * 4 + 3]) * (1.f / 128.f) - mub * mub;
        float rsb = rsqrtf(varb + 1e-5f);
        int rowa = row0 + ra, rowb = row0 + rb;
#pragma unroll
        for (int t = 0; t < 8; t++) {
            int col = nh * 64 + t * 8 + (lane & 3) * 2;
            float oax = elu1((c[t][0] - mua) * rsa * lngs[col]     + lnbs[col]);
            float oay = elu1((c[t][1] - mua) * rsa * lngs[col + 1] + lnbs[col + 1]);
            float obx = elu1((c[t][2] - mub) * rsb * lngs[col]     + lnbs[col]);
            float oby = elu1((c[t][3] - mub) * rsb * lngs[col + 1] + lnbs[col + 1]);
            if (rowa < N_NODES) *(float2*)&out_x[(size_t)rowa * DIM + col] = make_float2(oax, oay);
            if (rowb < N_NODES) *(float2*)&out_x[(size_t)rowb * DIM + col] = make_float2(obx, oby);
            uint32_t uh, ul;
            split2(oax, oay, uh, ul);
            *(uint32_t*)(sm + OFF_AH + ra * ASTR + col * 2) = uh;
            *(uint32_t*)(sm + OFF_AL + ra * ASTR + col * 2) = ul;
            split2(obx, oby, uh, ul);
            *(uint32_t*)(sm + OFF_AH + rb * ASTR + col * 2) = uh;
            *(uint32_t*)(sm + OFF_AL + rb * ASTR + col * 2) = ul;
        }
    }
    __syncthreads();

    // ---- second MMA: PQ = out_x @ [WeL|WeR]^T (out 256 cols) ----
    uint32_t bLaneN2 = ((lane >> 4) & 1) * 16 + nh * 256;
    float c2[16][4];
#pragma unroll
    for (int t = 0; t < 16; t++)
#pragma unroll
        for (int q = 0; q < 4; q++) c2[t][q] = 0.f;

#pragma unroll
    for (int kst = 0; kst < 8; kst++) {
        uint32_t ah[4], al[4];
        ldmx4(ah, aAddrH + kst * 32);
        ldmx4(al, aAddrL + kst * 32);
        uint32_t bAddr = sb + OFF_BH + (kst * 16 + bLaneRow) * 528 + bLaneN2;
#pragma unroll
        for (int tp = 0; tp < 8; tp++) {
            uint32_t bh[4], bl[4];
            ldmx4t(bh, bAddr + tp * 32);
            ldmx4t(bl, bAddr + tp * 32 + 67584);
            mma16816(c2[2 * tp],     ah, bh[0], bh[1]);
            mma16816(c2[2 * tp],     al, bh[0], bh[1]);
            mma16816(c2[2 * tp],     ah, bl[0], bl[1]);
            mma16816(c2[2 * tp + 1], ah, bh[2], bh[3]);
            mma16816(c2[2 * tp + 1], al, bh[2], bh[3]);
            mma16816(c2[2 * tp + 1], ah, bl[2], bl[3]);
        }
    }

    int rbase = row0 + mrow0 + (lane >> 2);
    int cbase = nh * 128 + (lane & 3) * 2;
#pragma unroll
    for (int t = 0; t < 16; t++) {
        int n0 = cbase + t * 8;
        if (rbase < N_NODES)     *(float2*)&g_PQ[(size_t)rbase * 256 + n0]       = make_float2(c2[t][0], c2[t][1]);
        if (rbase + 8 < N_NODES) *(float2*)&g_PQ[(size_t)(rbase + 8) * 256 + n0] = make_float2(c2[t][2], c2[t][3]);
    }
}

// ---------------- edge_out: warp per node; 2 edges per iteration (16 lanes each) ----------------
__global__ void __launch_bounds__(256) edge_out(
    const float* __restrict__ be, const float* __restrict__ lng, const float* __restrict__ lnb,
    float* __restrict__ out_e)
{
    int gw = (blockIdx.x * 256 + threadIdx.x) >> 5;   // node
    int lane = threadIdx.x & 31;
    if (gw >= N_NODES) return;
    int half = lane >> 4, cl = lane & 15;
    int j0 = cl * 8;

    float4 gv0 = *(const float4*)(lng + j0), gv1 = *(const float4*)(lng + j0 + 4);
    float4 bv0 = *(const float4*)(lnb + j0), bv1 = *(const float4*)(lnb + j0 + 4);
    float4 qb0, qb1;
    {
        float4 be0 = *(const float4*)(be + j0), be1 = *(const float4*)(be + j0 + 4);
        float4 qv0 = *(const float4*)&g_PQ[(size_t)gw * 256 + 128 + j0];
        float4 qv1 = *(const float4*)&g_PQ[(size_t)gw * 256 + 128 + j0 + 4];
        qb0.x = qv0.x + be0.x; qb0.y = qv0.y + be0.y; qb0.z = qv0.z + be0.z; qb0.w = qv0.w + be0.w;
        qb1.x = qv1.x + be1.x; qb1.y = qv1.y + be1.y; qb1.z = qv1.z + be1.z; qb1.w = qv1.w + be1.w;
    }
    int beg = g_off[gw];
    int end = (gw == N_NODES - 1) ? N_EDGES : g_off[gw + 1];

    for (int b = beg; b < end; b += 32) {
        int j = b + lane;
        int sl = 0, el = 0;
        if (j < end) { float4 e4 = g_edge[j]; sl = __float_as_int(e4.x); el = __float_as_int(e4.z); }
        int cnt = min(32, end - b);
        for (int q = 0; q < cnt; q += 2) {
            int idx = q + half;                       // <= 31 always
            int s_e = __shfl_sync(0xffffffffu, sl, idx);
            int e_e = __shfl_sync(0xffffffffu, el, idx);
            bool valid = idx < cnt;                   // half=1 may be past end (s_e=0 row read is safe)
            const float4* pp = (const float4*)&g_PQ[(size_t)s_e * 256 + j0];
            float4 p0 = pp[0], p1 = pp[1];
            float g0 = fgelu(p0.x + qb0.x);
            float g1 = fgelu(p0.y + qb0.y);
            float g2 = fgelu(p0.z + qb0.z);
            float g3 = fgelu(p0.w + qb0.w);
            float g4 = fgelu(p1.x + qb1.x);
            float g5 = fgelu(p1.y + qb1.y);
            float g6 = fgelu(p1.z + qb1.z);
            float g7 = fgelu(p1.w + qb1.w);
            float s1 = g0 + g1 + g2 + g3 + g4 + g5 + g6 + g7;
            float s2 = g0 * g0 + g1 * g1 + g2 * g2 + g3 * g3
                     + g4 * g4 + g5 * g5 + g6 * g6 + g7 * g7;
#pragma unroll
            for (int o = 1; o < 16; o <<= 1) {        // reduce within 16-lane half
                s1 += __shfl_xor_sync(0xffffffffu, s1, o);
                s2 += __shfl_xor_sync(0xffffffffu, s2, o);
            }
            float mu = s1 * (1.f / 128.f);
            float var = s2 * (1.f / 128.f) - mu * mu;
            float rstd = rsqrtf(var + 1e-5f);
            if (valid) {
                float4 o0, o1;
                o0.x = (g0 - mu) * rstd * gv0.x + bv0.x;
                o0.y = (g1 - mu) * rstd * gv0.y + bv0.y;
                o0.z = (g2 - mu) * rstd * gv0.z + bv0.z;
                o0.w = (g3 - mu) * rstd * gv0.w + bv0.w;
                o1.x = (g4 - mu) * rstd * gv1.x + bv1.x;
                o1.y = (g5 - mu) * rstd * gv1.y + bv1.y;
                o1.z = (g6 - mu) * rstd * gv1.z + bv1.z;
                o1.w = (g7 - mu) * rstd * gv1.w + bv1.w;
                float4* op = (float4*)(out_e + (size_t)e_e * DIM + j0);
                op[0] = o0;
                op[1] = o1;
            }
        }
    }
}

// ---------------- launch ----------------
extern "C" void kernel_launch(void* const* d_in, const int* in_sizes, int n_in,
                              void* d_out, int out_size)
{
    const float* x      = (const float*)d_in[0];
    const int*   ei     = (const int*)  d_in[1];
    const float* ea     = (const float*)d_in[2];
    const float* W_edge = (const float*)d_in[3];
    const float* tptr   = (const float*)d_in[4];
    const float* W1     = (const float*)d_in[5];
    const float* bng    = (const float*)d_in[6];
    const float* bnb    = (const float*)d_in[7];
    const float* W2     = (const float*)d_in[8];
    const float* lng    = (const float*)d_in[9];
    const float* lnb    = (const float*)d_in[10];
    const float* We     = (const float*)d_in[11];
    const float* be     = (const float*)d_in[12];
    const float* lneg   = (const float*)d_in[13];
    const float* lneb   = (const float*)d_in[14];

    const int* src = ei;
    const int* dst = ei + N_EDGES;

    float* out_x = (float*)d_out;
    float* out_e = out_x + (size_t)N_NODES * DIM;

    void *bnp, *b1h, *b1l, *ghp, *h1p;
    cudaGetSymbolAddress(&bnp, g_bnsum);
    cudaGetSymbolAddress(&b1h, g_B1h);
    cudaGetSymbolAddress(&b1l, g_B1l);
    cudaGetSymbolAddress(&ghp, g_h);
    cudaGetSymbolAddress(&h1p, g_h1);

    cudaFuncSetAttribute(tc256, cudaFuncAttributeMaxDynamicSharedMemorySize, SM_TC256);
    cudaFuncSetAttribute(tc_mlp2pq, cudaFuncAttributeMaxDynamicSharedMemorySize, SM_MLP2);

    int eblocks256 = (N_EDGES + 255) / 256;
    int ablocks = (N_NODES * 32 + 255) / 256;
    int tblocks = (N_NODES + 127) / 128;

    prep_all<<<384 + 196, 256>>>(W1, We, W2);                    // also zeros g_cnt
    hist<<<eblocks256, 256>>>(dst);
    scan50k<<<1, 1024>>>();
    scatter<<<eblocks256, 256>>>(src, dst, ea);
    aggregate<<<ablocks, 256>>>(x, W_edge, tptr);
    cudaMemsetAsync(bnp, 0, sizeof(float) * 512, 0);

    tc256<<<tblocks, 512, SM_TC256>>>((const float*)ghp, (const u16*)b1h, (const u16*)b1l, (float*)h1p);
    bn_reduce<<<200, 256>>>();
    bn_stat<<<1, 256>>>(bng, bnb);
    tc_mlp2pq<<<tblocks, 512, SM_MLP2>>>(lng, lnb, out_x);
    edge_out<<<ablocks, 256>>>(be, lneg, lneb, out_e);
}

// round 13
// speedup vs baseline: 1.2709x; 1.0551x over previous
#include <cuda_runtime.h>
#include <cuda_fp16.h>
#include <math.h>
#include <stdint.h>

#define N_NODES 50000
#define N_EDGES 800000
#define DIM 128

typedef unsigned long long ull;
typedef unsigned short u16;

// ---------------- scratch ----------------
__device__ float g_h[(size_t)N_NODES * DIM];         // aggr + x  (gemm1 input)
__device__ float g_h1[(size_t)N_NODES * 256];        // h @ W1.T
__device__ float g_PQ[(size_t)N_NODES * 256];        // [P | Q] per node
__device__ float4 g_edge[(size_t)N_EDGES];           // sorted (src_asf, ea, eid_asf, 0)
__device__ int g_cnt[N_NODES];
__device__ int g_off[N_NODES];
__device__ int g_cur[N_NODES];
__device__ float g_bnsum[512];
__device__ float g_bnstat[512];
// fp16 weights, [k][n] layout, padded rows (B is plain fp16; A carries hi/lo)
__device__ __align__(16) u16 g_B1h[128 * 264];       // W1:  k<128, n<256, stride 264
__device__ __align__(16) u16 g_B3h[128 * 264];       // We-remap: k<128, n<256
__device__ __align__(16) u16 g_B2h[256 * 136];       // W2:  k<256, n<128, stride 136

// ---------------- mma helpers ----------------
__device__ __forceinline__ uint32_t smem_u32(const void* p) {
    uint32_t a;
    asm("{ .reg .u64 t; cvta.to.shared.u64 t, %1; cvt.u32.u64 %0, t; }" : "=r"(a) : "l"(p));
    return a;
}
__device__ __forceinline__ void ldmx4(uint32_t* r, uint32_t addr) {
    asm volatile("ldmatrix.sync.aligned.m8n8.x4.shared.b16 {%0,%1,%2,%3}, [%4];"
        : "=r"(r[0]), "=r"(r[1]), "=r"(r[2]), "=r"(r[3]) : "r"(addr));
}
__device__ __forceinline__ void ldmx4t(uint32_t* r, uint32_t addr) {
    asm volatile("ldmatrix.sync.aligned.m8n8.x4.trans.shared.b16 {%0,%1,%2,%3}, [%4];"
        : "=r"(r[0]), "=r"(r[1]), "=r"(r[2]), "=r"(r[3]) : "r"(addr));
}
__device__ __forceinline__ void mma16816(float* c, const uint32_t* a, uint32_t b0, uint32_t b1) {
    asm volatile("mma.sync.aligned.m16n8k16.row.col.f32.f16.f16.f32 "
        "{%0,%1,%2,%3}, {%4,%5,%6,%7}, {%8,%9}, {%0,%1,%2,%3};"
        : "+f"(c[0]), "+f"(c[1]), "+f"(c[2]), "+f"(c[3])
        : "r"(a[0]), "r"(a[1]), "r"(a[2]), "r"(a[3]), "r"(b0), "r"(b1));
}
__device__ __forceinline__ void split2(float a, float b, uint32_t& uh, uint32_t& ul) {
    __half h0 = __float2half_rn(a), h1 = __float2half_rn(b);
    float r0 = a - __half2float(h0), r1 = b - __half2float(h1);
    __half l0 = __float2half_rn(r0), l1 = __float2half_rn(r1);
    uh = (uint32_t)(*(u16*)&h0) | ((uint32_t)(*(u16*)&h1) << 16);
    ul = (uint32_t)(*(u16*)&l0) | ((uint32_t)(*(u16*)&l1) << 16);
}

// fast exact GELU: erf via Abramowitz-Stegun 7.1.26 (|abs err| <= 1.5e-7)
__device__ __forceinline__ float fgelu(float v) {
    float x = fabsf(v) * 0.70710678118654752f;
    float t = __fdividef(1.0f, fmaf(0.3275911f, x, 1.0f));
    float poly = t * fmaf(t, fmaf(t, fmaf(t, fmaf(t, 1.061405429f, -1.453152027f),
                  1.421413741f), -0.284496736f), 0.254829592f);
    float ex = __expf(-x * x);
    float erf_abs = fmaf(-poly, ex, 1.0f);
    float erf_v = copysignf(erf_abs, v);
    return 0.5f * v * (1.0f + erf_v);
}

// SMEM layout (bytes)
#define CTRL 4096
#define ASTR 272                       // A row stride: 128 fp16 + 8 pad
#define OFF_AH CTRL
#define OFF_AL (OFF_AH + 128 * ASTR)
#define OFF_BH (OFF_AL + 128 * ASTR)   // 73728
#define SM_TC256 (OFF_BH + 67584)
#define SM_MLP2  (OFF_BH + 69632)      // also holds B3 later (67584)

// ---------------- weight prep + cnt zeroing (single kernel) ----------------
__global__ void __launch_bounds__(256) prep_all(
    const float* __restrict__ W1, const float* __restrict__ We, const float* __restrict__ W2)
{
    int b = blockIdx.x;
    if (b >= 384) {      // zero g_cnt
        int i = (b - 384) * 256 + threadIdx.x;
        if (i < N_NODES) g_cnt[i] = 0;
        return;
    }
    int li = (b % 128) * 256 + threadIdx.x;
    if (b < 256) {   // W1 (b<128) or We (128<=b<256): out [k<128][n<256] stride 264
        int j = li >> 7, k = li & 127;
        float v = (b < 128) ? W1[j * 128 + k]
                : ((j < 128) ? We[j * 256 + k] : We[(j - 128) * 256 + 128 + k]);
        __half hb = __float2half_rn(v);
        u16* Bh = (b < 128) ? g_B1h : g_B3h;
        Bh[k * 264 + j] = *(u16*)&hb;
    } else {         // W2: out [k<256][n<128] stride 136
        int j = li >> 8, k = li & 255;
        __half hb = __float2half_rn(W2[j * 256 + k]);
        g_B2h[k * 136 + j] = *(u16*)&hb;
    }
}

// ---------------- edge sort: hist / scan / scatter ----------------
__global__ void __launch_bounds__(256) hist(const int* __restrict__ dst)
{
    int e = blockIdx.x * 256 + threadIdx.x;
    if (e < N_EDGES) atomicAdd(&g_cnt[dst[e]], 1);
}

__global__ void __launch_bounds__(1024) scan50k()
{
    __shared__ int wsum[32];
    __shared__ int sh_carry;
    int tid = threadIdx.x, lane = tid & 31, w = tid >> 5;
    if (tid == 0) sh_carry = 0;
    __syncthreads();
    for (int base = 0; base < N_NODES; base += 1024) {
        int i = base + tid;
        int v = (i < N_NODES) ? g_cnt[i] : 0;
        int x = v;
#pragma unroll
        for (int o = 1; o < 32; o <<= 1) { int y = __shfl_up_sync(~0u, x, o); if (lane >= o) x += y; }
        if (lane == 31) wsum[w] = x;
        __syncthreads();
        if (w == 0) {
            int s = wsum[lane];
#pragma unroll
            for (int o = 1; o < 32; o <<= 1) { int y = __shfl_up_sync(~0u, s, o); if (lane >= o) s += y; }
            wsum[lane] = s;
        }
        __syncthreads();
        int warp_excl = (w == 0) ? 0 : wsum[w - 1];
        int carry = sh_carry;
        int excl = carry + warp_excl + x - v;
        if (i < N_NODES) { g_off[i] = excl; g_cur[i] = excl; }
        __syncthreads();
        if (tid == 1023) sh_carry = carry + wsum[31];
        __syncthreads();
    }
}

__global__ void __launch_bounds__(256) scatter(
    const int* __restrict__ src, const int* __restrict__ dst, const float* __restrict__ ea)
{
    int e = blockIdx.x * 256 + threadIdx.x;
    if (e >= N_EDGES) return;
    int d = dst[e];
    int pos = atomicAdd(&g_cur[d], 1);
    g_edge[pos] = make_float4(__int_as_float(src[e]), ea[e], __int_as_float(e), 0.f);
}

// ---------------- aggregate: warp per node, prefetched gather ----------------
__global__ void __launch_bounds__(256) aggregate(
    const float* __restrict__ x, const float* __restrict__ W_edge, const float* __restrict__ tptr)
{
    int gw = (blockIdx.x * 256 + threadIdx.x) >> 5;
    int lane = threadIdx.x & 31;
    if (gw >= N_NODES) return;
    const float t = tptr[0];
    float4 w4 = *(const float4*)&W_edge[lane * 4];

    int beg = g_off[gw];
    int end = (gw == N_NODES - 1) ? N_EDGES : g_off[gw + 1];

    float4 aE = make_float4(0.f, 0.f, 0.f, 0.f);
    float4 aM = make_float4(0.f, 0.f, 0.f, 0.f);

    for (int b = beg; b < end; b += 32) {
        int j = b + lane;
        float2 ed = make_float2(0.f, 0.f);
        if (j < end) { float4 e4 = g_edge[j]; ed = make_float2(e4.x, e4.y); }
        int cnt = min(32, end - b);
        int s_cur = __shfl_sync(0xffffffffu, __float_as_int(ed.x), 0);
        float a_cur = __shfl_sync(0xffffffffu, ed.y, 0);
        float4 xv = *(const float4*)&x[(size_t)s_cur * DIM + lane * 4];
        for (int q = 0; q < cnt; q++) {
            float4 xv_n = xv;
            float a_n = a_cur;
            if (q + 1 < cnt) {
                int s_n = __shfl_sync(0xffffffffu, __float_as_int(ed.x), q + 1);
                a_n = __shfl_sync(0xffffffffu, ed.y, q + 1);
                xv_n = *(const float4*)&x[(size_t)s_n * DIM + lane * 4];
            }
            float a = a_cur;
            float m0 = fmaxf(fmaf(a, w4.x, xv.x), 0.f) + 1e-7f;
            float m1 = fmaxf(fmaf(a, w4.y, xv.y), 0.f) + 1e-7f;
            float m2 = fmaxf(fmaf(a, w4.z, xv.z), 0.f) + 1e-7f;
            float m3 = fmaxf(fmaf(a, w4.w, xv.w), 0.f) + 1e-7f;
            float e0 = __expf(m0 * t), e1 = __expf(m1 * t);
            float e2 = __expf(m2 * t), e3 = __expf(m3 * t);
            aE.x += e0; aE.y += e1; aE.z += e2; aE.w += e3;
            aM.x = fmaf(m0, e0, aM.x); aM.y = fmaf(m1, e1, aM.y);
            aM.z = fmaf(m2, e2, aM.z); aM.w = fmaf(m3, e3, aM.w);
            xv = xv_n;
            a_cur = a_n;
        }
    }
    float4 xn = *(const float4*)&x[(size_t)gw * DIM + lane * 4];
    float4 h;
    h.x = aM.x / (aE.x + 1e-16f) + xn.x;
    h.y = aM.y / (aE.y + 1e-16f) + xn.y;
    h.z = aM.z / (aE.z + 1e-16f) + xn.z;
    h.w = aM.w / (aE.w + 1e-16f) + xn.w;
    *(float4*)&g_h[(size_t)gw * DIM + lane * 4] = h;
}

// ============================================================================
// tc256: g_h1[rows x 256] = g_h[rows x 128] @ W1[256 x 128]^T
// fp16 A hi/lo + fp16 B, 2-term compensation: Ah*B + Al*B
// ============================================================================
__global__ void __launch_bounds__(512, 1) tc256(
    const float* __restrict__ in, const u16* __restrict__ Bh, float* __restrict__ out)
{
    extern __shared__ __align__(16) char sm[];
    uint32_t sb = smem_u32(sm);
    int tid = threadIdx.x, wid = tid >> 5, lane = tid & 31;
    int row0 = blockIdx.x * 128;

    {
        const float4* bh = (const float4*)Bh;
        float4* sh = (float4*)(sm + OFF_BH);
        for (int i = tid; i < 4224; i += 512) sh[i] = bh[i];
    }
    for (int i = tid; i < 128 * 64; i += 512) {
        int r = i >> 6, k2 = (i & 63) << 1;
        int row = row0 + r;
        float2 hv = make_float2(0.f, 0.f);
        if (row < N_NODES) hv = *(const float2*)&in[(size_t)row * 128 + k2];
        uint32_t uh, ul;
        split2(hv.x, hv.y, uh, ul);
        *(uint32_t*)(sm + OFF_AH + r * ASTR + k2 * 2) = uh;
        *(uint32_t*)(sm + OFF_AL + r * ASTR + k2 * 2) = ul;
    }
    __syncthreads();

    int mrow0 = (wid & 7) * 16, nh = wid >> 3;
    uint32_t aRow = mrow0 + (lane & 7) + ((lane >> 3) & 1) * 8;
    uint32_t aAddrH = sb + OFF_AH + aRow * ASTR + (lane >> 4) * 16;
    uint32_t aAddrL = aAddrH + (OFF_AL - OFF_AH);
    uint32_t bLaneRow = (lane & 7) + ((lane >> 3) & 1) * 8;
    uint32_t bLaneN = ((lane >> 4) & 1) * 16 + nh * 256;

    float c[16][4];
#pragma unroll
    for (int t = 0; t < 16; t++)
#pragma unroll
        for (int q = 0; q < 4; q++) c[t][q] = 0.f;

#pragma unroll
    for (int kst = 0; kst < 8; kst++) {
        uint32_t ah[4], al[4];
        ldmx4(ah, aAddrH + kst * 32);
        ldmx4(al, aAddrL + kst * 32);
        uint32_t bAddr = sb + OFF_BH + (kst * 16 + bLaneRow) * 528 + bLaneN;
#pragma unroll
        for (int tp = 0; tp < 8; tp++) {
            uint32_t bh[4];
            ldmx4t(bh, bAddr + tp * 32);
            mma16816(c[2 * tp],     ah, bh[0], bh[1]);
            mma16816(c[2 * tp],     al, bh[0], bh[1]);
            mma16816(c[2 * tp + 1], ah, bh[2], bh[3]);
            mma16816(c[2 * tp + 1], al, bh[2], bh[3]);
        }
    }

    int rbase = row0 + mrow0 + (lane >> 2);
    int cbase = nh * 128 + (lane & 3) * 2;
#pragma unroll
    for (int t = 0; t < 16; t++) {
        int n0 = cbase + t * 8;
        if (rbase < N_NODES)     *(float2*)&out[(size_t)rbase * 256 + n0]       = make_float2(c[t][0], c[t][1]);
        if (rbase + 8 < N_NODES) *(float2*)&out[(size_t)(rbase + 8) * 256 + n0] = make_float2(c[t][2], c[t][3]);
    }
}

// ---------------- bn column reduction over g_h1 ----------------
__global__ void __launch_bounds__(256) bn_reduce()
{
    int t = threadIdx.x;
    int r0 = blockIdx.x * 250, r1 = min(r0 + 250, N_NODES);
    float s = 0.f, q = 0.f;
    for (int row = r0; row < r1; row++) {
        float v = g_h1[(size_t)row * 256 + t];
        s += v; q += v * v;
    }
    atomicAdd(&g_bnsum[t], s);
    atomicAdd(&g_bnsum[256 + t], q);
}

__global__ void bn_stat(const float* __restrict__ bng, const float* __restrict__ bnb)
{
    int j = threadIdx.x;
    float s = g_bnsum[j], s2 = g_bnsum[256 + j];
    float mu = s * (1.0f / N_NODES);
    float var = s2 * (1.0f / N_NODES) - mu * mu;
    float rstd = rsqrtf(var + 1e-5f);
    float sc = rstd * bng[j];
    g_bnstat[j] = sc;
    g_bnstat[256 + j] = bnb[j] - mu * sc;
}

__device__ __forceinline__ float elu1(float v) { return v > 0.f ? v : expm1f(v); }

// ============================================================================
// tc_mlp2pq: out_x = ELU(LN(relu(bn(g_h1)) @ W2.T)); then PQ = out_x @ We' in-kernel
// ============================================================================
__global__ void __launch_bounds__(512, 1) tc_mlp2pq(
    const float* __restrict__ lng, const float* __restrict__ lnb, float* __restrict__ out_x)
{
    extern __shared__ __align__(16) char sm[];
    uint32_t sb = smem_u32(sm);
    int tid = threadIdx.x, wid = tid >> 5, lane = tid & 31;
    int row0 = blockIdx.x * 128;

    float* red  = (float*)sm;            // [128][4]
    float* lngs = (float*)(sm + 2048);
    float* lnbs = (float*)(sm + 2560);
    if (tid < 128) { lngs[tid] = lng[tid]; lnbs[tid] = lnb[tid]; }

    {
        const float4* bh = (const float4*)g_B2h;
        float4* sh = (float4*)(sm + OFF_BH);
        for (int i = tid; i < 4352; i += 512) sh[i] = bh[i];
    }

    int mrow0 = (wid & 7) * 16, nh = wid >> 3;
    uint32_t aRow = mrow0 + (lane & 7) + ((lane >> 3) & 1) * 8;
    uint32_t aAddrH = sb + OFF_AH + aRow * ASTR + (lane >> 4) * 16;
    uint32_t aAddrL = aAddrH + (OFF_AL - OFF_AH);
    uint32_t bLaneRow = (lane & 7) + ((lane >> 3) & 1) * 8;
    uint32_t bLaneN = ((lane >> 4) & 1) * 16 + nh * 128;

    float c[8][4];
#pragma unroll
    for (int t = 0; t < 8; t++)
#pragma unroll
        for (int q = 0; q < 4; q++) c[t][q] = 0.f;

#pragma unroll
    for (int s = 0; s < 2; s++) {
        __syncthreads();
        for (int i = tid; i < 128 * 64; i += 512) {
            int r = i >> 6, k2 = (i & 63) << 1;
            int row = row0 + r;
            float v0 = 0.f, v1 = 0.f;
            if (row < N_NODES) {
                int kc = s * 128 + k2;
                float2 hv = *(const float2*)&g_h1[(size_t)row * 256 + kc];
                v0 = fmaxf(fmaf(hv.x, g_bnstat[kc],     g_bnstat[256 + kc]),     0.f);
                v1 = fmaxf(fmaf(hv.y, g_bnstat[kc + 1], g_bnstat[256 + kc + 1]), 0.f);
            }
            uint32_t uh, ul;
            split2(v0, v1, uh, ul);
            *(uint32_t*)(sm + OFF_AH + r * ASTR + k2 * 2) = uh;
            *(uint32_t*)(sm + OFF_AL + r * ASTR + k2 * 2) = ul;
        }
        __syncthreads();

#pragma unroll
        for (int kst = 0; kst < 8; kst++) {
            uint32_t ah[4], al[4];
            ldmx4(ah, aAddrH + kst * 32);
            ldmx4(al, aAddrL + kst * 32);
            uint32_t bAddr = sb + OFF_BH + (s * 128 + kst * 16 + bLaneRow) * 272 + bLaneN;
#pragma unroll
            for (int tp = 0; tp < 4; tp++) {
                uint32_t bh[4];
                ldmx4t(bh, bAddr + tp * 32);
                mma16816(c[2 * tp],     ah, bh[0], bh[1]);
                mma16816(c[2 * tp],     al, bh[0], bh[1]);
                mma16816(c[2 * tp + 1], ah, bh[2], bh[3]);
                mma16816(c[2 * tp + 1], al, bh[2], bh[3]);
            }
        }
    }

    // ---- barrier: everyone done reading B2, load B3 over it ----
    __syncthreads();
    {
        const float4* bh = (const float4*)g_B3h;
        float4* sh = (float4*)(sm + OFF_BH);
        for (int i = tid; i < 4224; i += 512) sh[i] = bh[i];
    }

    // ---- LN + ELU epilogue; write out_x AND fp16-split into A smem ----
    float s1a = 0.f, s2a = 0.f, s1b = 0.f, s2b = 0.f;
#pragma unroll
    for (int t = 0; t < 8; t++) {
        s1a += c[t][0] + c[t][1];
        s2a += c[t][0] * c[t][0] + c[t][1] * c[t][1];
        s1b += c[t][2] + c[t][3];
        s2b += c[t][2] * c[t][2] + c[t][3] * c[t][3];
    }
#pragma unroll
    for (int o = 1; o < 4; o <<= 1) {
        s1a += __shfl_xor_sync(~0u, s1a, o);
        s2a += __shfl_xor_sync(~0u, s2a, o);
        s1b += __shfl_xor_sync(~0u, s1b, o);
        s2b += __shfl_xor_sync(~0u, s2b, o);
    }
    __syncthreads();
    if ((lane & 3) == 0) {
        int r = mrow0 + (lane >> 2);
        red[r * 4 + nh * 2]           = s1a;
        red[r * 4 + nh * 2 + 1]       = s2a;
        red[(r + 8) * 4 + nh * 2]     = s1b;
        red[(r + 8) * 4 + nh * 2 + 1] = s2b;
    }
    __syncthreads();
    {
        int ra = mrow0 + (lane >> 2), rb = ra + 8;
        float mua = (red[ra * 4] + red[ra * 4 + 2]) * (1.f / 128.f);
        float vara = (red[ra * 4 + 1] + red[ra * 4 + 3]) * (1.f / 128.f) - mua * mua;
        float rsa = rsqrtf(vara + 1e-5f);
        float mub = (red[rb * 4] + red[rb * 4 + 2]) * (1.f / 128.f);
        float varb = (red[rb * 4 + 1] + red[rb * 4 + 3]) * (1.f / 128.f) - mub * mub;
        float rsb = rsqrtf(varb + 1e-5f);
        int rowa = row0 + ra, rowb = row0 + rb;
#pragma unroll
        for (int t = 0; t < 8; t++) {
            int col = nh * 64 + t * 8 + (lane & 3) * 2;
            float oax = elu1((c[t][0] - mua) * rsa * lngs[col]     + lnbs[col]);
            float oay = elu1((c[t][1] - mua) * rsa * lngs[col + 1] + lnbs[col + 1]);
            float obx = elu1((c[t][2] - mub) * rsb * lngs[col]     + lnbs[col]);
            float oby = elu1((c[t][3] - mub) * rsb * lngs[col + 1] + lnbs[col + 1]);
            if (rowa < N_NODES) *(float2*)&out_x[(size_t)rowa * DIM + col] = make_float2(oax, oay);
            if (rowb < N_NODES) *(float2*)&out_x[(size_t)rowb * DIM + col] = make_float2(obx, oby);
            uint32_t uh, ul;
            split2(oax, oay, uh, ul);
            *(uint32_t*)(sm + OFF_AH + ra * ASTR + col * 2) = uh;
            *(uint32_t*)(sm + OFF_AL + ra * ASTR + col * 2) = ul;
            split2(obx, oby, uh, ul);
            *(uint32_t*)(sm + OFF_AH + rb * ASTR + col * 2) = uh;
            *(uint32_t*)(sm + OFF_AL + rb * ASTR + col * 2) = ul;
        }
    }
    __syncthreads();

    // ---- second MMA: PQ = out_x @ [WeL|WeR]^T (out 256 cols) ----
    uint32_t bLaneN2 = ((lane >> 4) & 1) * 16 + nh * 256;
    float c2[16][4];
#pragma unroll
    for (int t = 0; t < 16; t++)
#pragma unroll
        for (int q = 0; q < 4; q++) c2[t][q] = 0.f;

#pragma unroll
    for (int kst = 0; kst < 8; kst++) {
        uint32_t ah[4], al[4];
        ldmx4(ah, aAddrH + kst * 32);
        ldmx4(al, aAddrL + kst * 32);
        uint32_t bAddr = sb + OFF_BH + (kst * 16 + bLaneRow) * 528 + bLaneN2;
#pragma unroll
        for (int tp = 0; tp < 8; tp++) {
            uint32_t bh[4];
            ldmx4t(bh, bAddr + tp * 32);
            mma16816(c2[2 * tp],     ah, bh[0], bh[1]);
            mma16816(c2[2 * tp],     al, bh[0], bh[1]);
            mma16816(c2[2 * tp + 1], ah, bh[2], bh[3]);
            mma16816(c2[2 * tp + 1], al, bh[2], bh[3]);
        }
    }

    int rbase = row0 + mrow0 + (lane >> 2);
    int cbase = nh * 128 + (lane & 3) * 2;
#pragma unroll
    for (int t = 0; t < 16; t++) {
        int n0 = cbase + t * 8;
        if (rbase < N_NODES)     *(float2*)&g_PQ[(size_t)rbase * 256 + n0]       = make_float2(c2[t][0], c2[t][1]);
        if (rbase + 8 < N_NODES) *(float2*)&g_PQ[(size_t)(rbase + 8) * 256 + n0] = make_float2(c2[t][2], c2[t][3]);
    }
}

// ---------------- edge_out: warp per node; 2 edges per iteration (16 lanes each) ----------------
__global__ void __launch_bounds__(256) edge_out(
    const float* __restrict__ be, const float* __restrict__ lng, const float* __restrict__ lnb,
    float* __restrict__ out_e)
{
    int gw = (blockIdx.x * 256 + threadIdx.x) >> 5;   // node
    int lane = threadIdx.x & 31;
    if (gw >= N_NODES) return;
    int half = lane >> 4, cl = lane & 15;
    int j0 = cl * 8;

    float4 gv0 = *(const float4*)(lng + j0), gv1 = *(const float4*)(lng + j0 + 4);
    float4 bv0 = *(const float4*)(lnb + j0), bv1 = *(const float4*)(lnb + j0 + 4);
    float4 qb0, qb1;
    {
        float4 be0 = *(const float4*)(be + j0), be1 = *(const float4*)(be + j0 + 4);
        float4 qv0 = *(const float4*)&g_PQ[(size_t)gw * 256 + 128 + j0];
        float4 qv1 = *(const float4*)&g_PQ[(size_t)gw * 256 + 128 + j0 + 4];
        qb0.x = qv0.x + be0.x; qb0.y = qv0.y + be0.y; qb0.z = qv0.z + be0.z; qb0.w = qv0.w + be0.w;
        qb1.x = qv1.x + be1.x; qb1.y = qv1.y + be1.y; qb1.z = qv1.z + be1.z; qb1.w = qv1.w + be1.w;
    }
    int beg = g_off[gw];
    int end = (gw == N_NODES - 1) ? N_EDGES : g_off[gw + 1];

    for (int b = beg; b < end; b += 32) {
        int j = b + lane;
        int sl = 0, el = 0;
        if (j < end) { float4 e4 = g_edge[j]; sl = __float_as_int(e4.x); el = __float_as_int(e4.z); }
        int cnt = min(32, end - b);
        for (int q = 0; q < cnt; q += 2) {
            int idx = q + half;
            int s_e = __shfl_sync(0xffffffffu, sl, idx);
            int e_e = __shfl_sync(0xffffffffu, el, idx);
            bool valid = idx < cnt;
            const float4* pp = (const float4*)&g_PQ[(size_t)s_e * 256 + j0];
            float4 p0 = pp[0], p1 = pp[1];
            float g0 = fgelu(p0.x + qb0.x);
            float g1 = fgelu(p0.y + qb0.y);
            float g2 = fgelu(p0.z + qb0.z);
            float g3 = fgelu(p0.w + qb0.w);
            float g4 = fgelu(p1.x + qb1.x);
            float g5 = fgelu(p1.y + qb1.y);
            float g6 = fgelu(p1.z + qb1.z);
            float g7 = fgelu(p1.w + qb1.w);
            float s1 = g0 + g1 + g2 + g3 + g4 + g5 + g6 + g7;
            float s2 = g0 * g0 + g1 * g1 + g2 * g2 + g3 * g3
                     + g4 * g4 + g5 * g5 + g6 * g6 + g7 * g7;
#pragma unroll
            for (int o = 1; o < 16; o <<= 1) {
                s1 += __shfl_xor_sync(0xffffffffu, s1, o);
                s2 += __shfl_xor_sync(0xffffffffu, s2, o);
            }
            float mu = s1 * (1.f / 128.f);
            float var = s2 * (1.f / 128.f) - mu * mu;
            float rstd = rsqrtf(var + 1e-5f);
            if (valid) {
                float4 o0, o1;
                o0.x = (g0 - mu) * rstd * gv0.x + bv0.x;
                o0.y = (g1 - mu) * rstd * gv0.y + bv0.y;
                o0.z = (g2 - mu) * rstd * gv0.z + bv0.z;
                o0.w = (g3 - mu) * rstd * gv0.w + bv0.w;
                o1.x = (g4 - mu) * rstd * gv1.x + bv1.x;
                o1.y = (g5 - mu) * rstd * gv1.y + bv1.y;
                o1.z = (g6 - mu) * rstd * gv1.z + bv1.z;
                o1.w = (g7 - mu) * rstd * gv1.w + bv1.w;
                float4* op = (float4*)(out_e + (size_t)e_e * DIM + j0);
                op[0] = o0;
                op[1] = o1;
            }
        }
    }
}

// ---------------- launch ----------------
extern "C" void kernel_launch(void* const* d_in, const int* in_sizes, int n_in,
                              void* d_out, int out_size)
{
    const float* x      = (const float*)d_in[0];
    const int*   ei     = (const int*)  d_in[1];
    const float* ea     = (const float*)d_in[2];
    const float* W_edge = (const float*)d_in[3];
    const float* tptr   = (const float*)d_in[4];
    const float* W1     = (const float*)d_in[5];
    const float* bng    = (const float*)d_in[6];
    const float* bnb    = (const float*)d_in[7];
    const float* W2     = (const float*)d_in[8];
    const float* lng    = (const float*)d_in[9];
    const float* lnb    = (const float*)d_in[10];
    const float* We     = (const float*)d_in[11];
    const float* be     = (const float*)d_in[12];
    const float* lneg   = (const float*)d_in[13];
    const float* lneb   = (const float*)d_in[14];

    const int* src = ei;
    const int* dst = ei + N_EDGES;

    float* out_x = (float*)d_out;
    float* out_e = out_x + (size_t)N_NODES * DIM;

    void *bnp, *b1h, *ghp, *h1p;
    cudaGetSymbolAddress(&bnp, g_bnsum);
    cudaGetSymbolAddress(&b1h, g_B1h);
    cudaGetSymbolAddress(&ghp, g_h);
    cudaGetSymbolAddress(&h1p, g_h1);

    cudaFuncSetAttribute(tc256, cudaFuncAttributeMaxDynamicSharedMemorySize, SM_TC256);
    cudaFuncSetAttribute(tc_mlp2pq, cudaFuncAttributeMaxDynamicSharedMemorySize, SM_MLP2);

    int eblocks256 = (N_EDGES + 255) / 256;
    int ablocks = (N_NODES * 32 + 255) / 256;
    int tblocks = (N_NODES + 127) / 128;

    prep_all<<<384 + 196, 256>>>(W1, We, W2);                    // also zeros g_cnt
    hist<<<eblocks256, 256>>>(dst);
    scan50k<<<1, 1024>>>();
    scatter<<<eblocks256, 256>>>(src, dst, ea);
    aggregate<<<ablocks, 256>>>(x, W_edge, tptr);
    cudaMemsetAsync(bnp, 0, sizeof(float) * 512, 0);

    tc256<<<tblocks, 512, SM_TC256>>>((const float*)ghp, (const u16*)b1h, (float*)h1p);
    bn_reduce<<<200, 256>>>();
    bn_stat<<<1, 256>>>(bng, bnb);
    tc_mlp2pq<<<tblocks, 512, SM_MLP2>>>(lng, lnb, out_x);
    edge_out<<<ablocks, 256>>>(be, lneg, lneb, out_e);
}